// round 13
// baseline (speedup 1.0000x reference)
#include <cuda_runtime.h>
#include <cuda_fp16.h>
#include <math.h>

// ---------------------------------------------------------------------------
// SpatialTransformerInputHead  (B=128, H=W=256, C=1)
//   conv1 5x5 1->14 + relu + maxpool2  (fp32 f32x2)         -> g_buf1 fp16 NHWC16
//   conv2 5x5 14->32 + relu + maxpool2 (fp16 HMMA, fp32 acc)-> g_buf2 fp16 NHWC
//   dense1 119072->120 (fp16 HMMA split-K), relu in dense23
//   dense 120->84 relu, 84->6 -> theta
//   bilinear grid sample + 1x1 conv + sigmoid -> [128,256,256,1]
// ---------------------------------------------------------------------------

typedef unsigned long long ull;
typedef unsigned int uint32;

#define BATCH 128
#define HW    256
#define P1    126
#define P2    61
#define FLAT  (61*61*32)   // 119072

#define D1_SPLITS 148
#define D1_KCHUNK 832      // 148*832 = 123136 >= FLAT, multiple of 32
#define D1_NKB    26       // 832/32

// --------- scratch -----------------------------------------------------------
__device__ __half g_buf1[(size_t)BATCH*P1*P1*16];  // conv1 pooled, NHWC16, fp16
__device__ __half g_w16[25*32*24];                 // conv2 weights fp16 [tap][co][k24]
__device__ __half g_buf2[(size_t)BATCH*FLAT];      // conv2 pooled, NHWC flat, fp16
__device__ float  g_part[(size_t)D1_SPLITS*BATCH*120];
__device__ float  g_theta[BATCH*6];

// --------- helpers -----------------------------------------------------------
__device__ __forceinline__ ull pk2(float v) {
    ull r;
    asm("mov.b64 %0, {%1, %2};" : "=l"(r) : "f"(v), "f"(v));
    return r;
}
__device__ __forceinline__ void upk2(ull v, float& lo, float& hi) {
    asm("mov.b64 {%0, %1}, %2;" : "=f"(lo), "=f"(hi) : "l"(v));
}
#define FMA2(d, a, b) asm("fma.rn.f32x2 %0, %1, %2, %0;" : "+l"(d) : "l"(a), "l"(b))

__device__ __forceinline__ uint32 smem_u32(const void* p) {
    uint32 a;
    asm("{ .reg .u64 t; cvta.to.shared.u64 t, %1; cvt.u32.u64 %0, t; }"
        : "=r"(a) : "l"(p));
    return a;
}

#define MMA_F16(c, a0, a1, a2, a3, b0, b1)                                     \
    asm volatile(                                                              \
        "mma.sync.aligned.m16n8k16.row.col.f32.f16.f16.f32 "                   \
        "{%0,%1,%2,%3}, {%4,%5,%6,%7}, {%8,%9}, {%0,%1,%2,%3};"                \
        : "+f"((c)[0]), "+f"((c)[1]), "+f"((c)[2]), "+f"((c)[3])               \
        : "r"(a0), "r"(a1), "r"(a2), "r"(a3), "r"(b0), "r"(b1))

#define LDSM_X4(r0, r1, r2, r3, addr)                                          \
    asm volatile("ldmatrix.sync.aligned.m8n8.x4.shared.b16 {%0,%1,%2,%3}, [%4];" \
        : "=r"(r0), "=r"(r1), "=r"(r2), "=r"(r3) : "r"(addr))

// ===========================================================================
// wprep: conv2 weights HWIO fp32 -> fp16 [tap][co(32)][ci pad 24], once.
// ===========================================================================
__global__ void __launch_bounds__(256) wprep_kernel(const float* __restrict__ w)
{
    const int tap = blockIdx.x;
    for (int i = threadIdx.x; i < 768; i += 256) {
        int n = i / 24, k = i - n*24;
        float v = (k < 14) ? w[tap*448 + k*32 + n] : 0.f;
        g_w16[tap*768 + i] = __float2half_rn(v);
    }
}

// ===========================================================================
// conv1 (5x5, 1->14) + relu + maxpool2, fp32 f32x2 math, fp16 NHWC16 output.
// grid (8,8,128), 256 threads.
// ===========================================================================
__global__ void __launch_bounds__(256) conv1_kernel(
    const float* __restrict__ x, const float* __restrict__ w,
    const float* __restrict__ bias)
{
    __shared__ __align__(16) float sw[352];
    __shared__ __align__(16) float sb[16];
    __shared__ __align__(16) float sin_[36*36];

    const int b  = blockIdx.z;
    const int ox = blockIdx.x * 32;
    const int oy = blockIdx.y * 32;
    const int tid = threadIdx.x;

    for (int i = tid; i < 350; i += 256) sw[i] = w[i];
    if (tid < 14)  sb[tid] = bias[tid];

    const float* xb = x + (size_t)b * (HW*HW);
    for (int i = tid; i < 36*36; i += 256) {
        int r = i / 36, c = i % 36;
        int gy = oy + r, gx = ox + c;
        sin_[i] = (gy < HW && gx < HW) ? xb[gy*HW + gx] : 0.f;
    }
    __syncthreads();

    const int tx = tid & 15, ty = tid >> 4;

    ull acc[4][7];
#pragma unroll
    for (int p = 0; p < 4; ++p)
#pragma unroll
        for (int j = 0; j < 7; ++j) acc[p][j] = 0ull;

    const float* ib = sin_ + (2*ty)*36 + 2*tx;
#pragma unroll
    for (int dy = 0; dy < 5; ++dy) {
        const float* ra = ib + dy*36;
        const float* rb = ra + 36;
#pragma unroll
        for (int dx = 0; dx < 5; ++dx) {
            ull p00 = pk2(ra[dx]);
            ull p01 = pk2(ra[dx+1]);
            ull p10 = pk2(rb[dx]);
            ull p11 = pk2(rb[dx+1]);
            const ull* wp = (const ull*)&sw[(dy*5 + dx)*14];
#pragma unroll
            for (int j = 0; j < 7; ++j) {
                ull wv = wp[j];
                FMA2(acc[0][j], p00, wv);
                FMA2(acc[1][j], p01, wv);
                FMA2(acc[2][j], p10, wv);
                FMA2(acc[3][j], p11, wv);
            }
        }
    }

    const int x0 = blockIdx.x*16 + tx;
    const int y0 = blockIdx.y*16 + ty;
    if (x0 < P1 && y0 < P1) {
        union { uint4 u[2]; __half2 h2[8]; } pk;
#pragma unroll
        for (int j = 0; j < 7; ++j) {
            float l0,h0,l1,h1,l2,h2,l3,h3;
            upk2(acc[0][j], l0, h0);
            upk2(acc[1][j], l1, h1);
            upk2(acc[2][j], l2, h2);
            upk2(acc[3][j], l3, h3);
            float m0 = fmaxf(fmaxf(l0,l1), fmaxf(l2,l3)) + sb[2*j];
            float m1 = fmaxf(fmaxf(h0,h1), fmaxf(h2,h3)) + sb[2*j+1];
            pk.h2[j] = __float22half2_rn(make_float2(fmaxf(m0, 0.f), fmaxf(m1, 0.f)));
        }
        pk.h2[7] = __float22half2_rn(make_float2(0.f, 0.f));
        uint4* dst = (uint4*)(g_buf1 + ((size_t)(b*P1 + y0)*P1 + x0)*16);
        dst[0] = pk.u[0];
        dst[1] = pk.u[1];
    }
}

// ===========================================================================
// conv2 via fp16 mma.sync m16n8k16 (fp32 accum): 5x5 conv = 25 shifted GEMMs.
// Block: 8x16 pooled, 256 threads (8 warps), 2 blocks/SM.
// Epilogue: 2x2 maxpool + bias + relu -> fp16 NHWC flat g_buf2.
// ===========================================================================
#define C2_A_B    (720*48)                  // 34560 B (20 rows x 36 cols)
#define C2_W_B    (25*32*48)                // 38400 B
#define C2_SMEM_B (C2_A_B + C2_W_B + 128)   // 73088 B

__global__ void __launch_bounds__(256, 2) conv2_kernel(const float* __restrict__ bias)
{
    extern __shared__ __align__(16) unsigned char smem[];
    __half* At = (__half*)smem;                        // [pos 20x36][24]
    __half* Wt = (__half*)(smem + C2_A_B);             // [tap][co32][24]
    float*  sb = (float*)(smem + C2_A_B + C2_W_B);     // [32]

    const int b   = blockIdx.z;
    const int px0 = blockIdx.x * 16;
    const int py0 = blockIdx.y * 8;
    const int ix0 = px0 * 2;
    const int iy0 = py0 * 2;
    const int tid = threadIdx.x;

    // W: straight 38.4KB vector copy from preconverted fp16
    {
        const uint4* ws = (const uint4*)g_w16;
        uint4* wd = (uint4*)Wt;
        for (int i = tid; i < C2_W_B/16; i += 256) wd[i] = ws[i];
    }
    if (tid < 32) sb[tid] = bias[tid];

    // A tile: 20x36 positions, 32B fp16 copy + 16B zero pad (48B rows)
    for (int p = tid; p < 720; p += 256) {
        int r = p / 36, c = p - r*36;
        int gy = iy0 + r, gx = ix0 + c;
        uint4 u0 = make_uint4(0,0,0,0), u1 = u0;
        if (gy < P1 && gx < P1) {
            const uint4* s4 = (const uint4*)(g_buf1 + ((size_t)(b*P1 + gy)*P1 + gx)*16);
            u0 = s4[0]; u1 = s4[1];
        }
        uint4* d = (uint4*)(At + p*24);
        d[0] = u0; d[1] = u1; d[2] = make_uint4(0,0,0,0);
    }
    __syncthreads();

    const int warp = tid >> 5, lane = tid & 31;
    const int y0 = 2 * warp;
    const uint32 atb = smem_u32(At);
    const uint32 wtb = smem_u32(Wt);

    const uint32 aoff = (uint32)((lane & 15)*48 + (lane >> 4)*16);
    const uint32 boff = (uint32)(((lane & 7) + ((lane >> 4) & 1)*8)*48
                                 + ((lane >> 3) & 1)*16);

    float cacc[2][2][4][4];
#pragma unroll
    for (int s = 0; s < 2; ++s)
#pragma unroll
        for (int xh = 0; xh < 2; ++xh)
#pragma unroll
            for (int nf = 0; nf < 4; ++nf)
#pragma unroll
                for (int k = 0; k < 4; ++k) cacc[s][xh][nf][k] = 0.f;

#pragma unroll 1
    for (int tap = 0; tap < 25; ++tap) {
        const int dy = tap / 5, dx = tap - 5*dy;

        const uint32 wb = wtb + (uint32)(tap*1536) + boff;
        uint32 b00, b01, b10, b11, b20, b21, b30, b31;
        LDSM_X4(b00, b01, b10, b11, wb);
        LDSM_X4(b20, b21, b30, b31, wb + 768);

#pragma unroll
        for (int s = 0; s < 2; ++s) {
            const int rowbase = (y0 + s + dy)*36 + dx;
#pragma unroll
            for (int xh = 0; xh < 2; ++xh) {
                uint32 a0, a1, a2, a3;
                LDSM_X4(a0, a1, a2, a3,
                        atb + (uint32)((rowbase + xh*16)*48) + aoff);
                MMA_F16(cacc[s][xh][0], a0, a1, a2, a3, b00, b01);
                MMA_F16(cacc[s][xh][1], a0, a1, a2, a3, b10, b11);
                MMA_F16(cacc[s][xh][2], a0, a1, a2, a3, b20, b21);
                MMA_F16(cacc[s][xh][3], a0, a1, a2, a3, b30, b31);
            }
        }
    }

    // epilogue: 2x2 maxpool + bias + relu -> fp16 NHWC
    const int py = py0 + warp;
    const int r  = lane >> 2;
    const bool active = ((r & 1) == 0);
    const int j = r >> 1;
    const int n0 = (lane & 3) * 2;

#pragma unroll
    for (int xh = 0; xh < 2; ++xh)
#pragma unroll
    for (int nf = 0; nf < 4; ++nf) {
        float m0 = fmaxf(cacc[0][xh][nf][0], cacc[1][xh][nf][0]);
        float m1 = fmaxf(cacc[0][xh][nf][1], cacc[1][xh][nf][1]);
        float m2 = fmaxf(cacc[0][xh][nf][2], cacc[1][xh][nf][2]);
        float m3 = fmaxf(cacc[0][xh][nf][3], cacc[1][xh][nf][3]);
        float o0 = fmaxf(m0, __shfl_down_sync(0xffffffffu, m0, 4));
        float o1 = fmaxf(m1, __shfl_down_sync(0xffffffffu, m1, 4));
        float o2 = fmaxf(m2, __shfl_down_sync(0xffffffffu, m2, 4));
        float o3 = fmaxf(m3, __shfl_down_sync(0xffffffffu, m3, 4));
        if (active && py < P2) {
            const int ch  = nf*8 + n0;
            const float b0v = sb[ch], b1v = sb[ch+1];
            const int pxa = px0 + xh*8 + j;
            const int pxb = pxa + 4;
            if (pxa < P2) {
                __half2 v = __float22half2_rn(
                    make_float2(fmaxf(o0 + b0v, 0.f), fmaxf(o1 + b1v, 0.f)));
                *(__half2*)(g_buf2 + (((size_t)b*P2 + py)*P2 + pxa)*32 + ch) = v;
            }
            if (pxb < P2) {
                __half2 v = __float22half2_rn(
                    make_float2(fmaxf(o2 + b0v, 0.f), fmaxf(o3 + b1v, 0.f)));
                *(__half2*)(g_buf2 + (((size_t)b*P2 + py)*P2 + pxb)*32 + ch) = v;
            }
        }
    }
}

// ===========================================================================
// dense1 via fp16 HMMA split-K:  [128 x K] @ [K x 120] -> fp32 partials.
// grid 148 blocks (one K-chunk of 832 each), 256 threads (8 warps).
// Warp w owns batch rows m = w*16..w*16+15, all 120 (pad 128) outputs.
// A: As[128 m][40 halfs] (80B stride, conflict-free LDSM), fp16 from g_buf2.
// B: Ws[128 n][40 halfs], fp16 converted in-block from d1_w (coalesced reads).
// ===========================================================================
__global__ void __launch_bounds__(256) dense1_kernel(const float* __restrict__ w)
{
    __shared__ __align__(16) __half As[128*40];
    __shared__ __align__(16) __half Ws[128*40];

    const int ks  = blockIdx.x * D1_KCHUNK;
    const int tid = threadIdx.x;
    const int wid = tid >> 5, lane = tid & 31;

    const uint32 atb = smem_u32(As);
    const uint32 wtb = smem_u32(Ws);
    const uint32 aoff = (uint32)(wid*1280 + (lane & 15)*80 + (lane >> 4)*16);
    const uint32 boff = (uint32)(((lane & 7) + ((lane >> 4) & 1)*8)*80
                                 + ((lane >> 3) & 1)*16);

    float acc[16][4];
#pragma unroll
    for (int f = 0; f < 16; ++f)
#pragma unroll
        for (int k = 0; k < 4; ++k) acc[f][k] = 0.f;

#pragma unroll 1
    for (int kb = 0; kb < D1_NKB; ++kb) {
        const int k0 = ks + kb*32;

        // A: 128 rows x 32 halfs = 512 16B chunks
        for (int i = tid; i < 512; i += 256) {
            int r = i >> 2, q = i & 3;
            int k = k0 + q*8;
            uint4 v = make_uint4(0,0,0,0);
            if (k < FLAT) v = *(const uint4*)(g_buf2 + (size_t)r*FLAT + k);
            *(uint4*)((unsigned char*)As + r*80 + q*16) = v;
        }
        // W: [n 128 pad][k 32], reads coalesced along n
        for (int i = tid; i < 4096; i += 256) {
            int kk = i >> 7, n = i & 127;
            int k = k0 + kk;
            float v = (n < 120 && k < FLAT) ? w[(size_t)k*120 + n] : 0.f;
            Ws[n*40 + kk] = __float2half_rn(v);
        }
        __syncthreads();

#pragma unroll
        for (int kc = 0; kc < 2; ++kc) {
            uint32 a0, a1, a2, a3;
            LDSM_X4(a0, a1, a2, a3, atb + aoff + (uint32)(kc*32));
#pragma unroll
            for (int j = 0; j < 8; ++j) {
                uint32 r0, r1, r2, r3;
                LDSM_X4(r0, r1, r2, r3,
                        wtb + (uint32)(j*1280) + boff + (uint32)(kc*32));
                MMA_F16(acc[2*j],   a0, a1, a2, a3, r0, r1);
                MMA_F16(acc[2*j+1], a0, a1, a2, a3, r2, r3);
            }
        }
        __syncthreads();
    }

    // store fp32 partials: g_part[(split*128 + m)*120 + n]  (skip n >= 120)
    const int r  = lane >> 2;
    const int c2 = (lane & 3) * 2;
    float* gp = g_part + ((size_t)blockIdx.x*BATCH + wid*16)*120;
#pragma unroll
    for (int nf = 0; nf < 15; ++nf) {
        int n = nf*8 + c2;
        *(float2*)(gp + (size_t)r*120 + n)     = make_float2(acc[nf][0], acc[nf][1]);
        *(float2*)(gp + (size_t)(r+8)*120 + n) = make_float2(acc[nf][2], acc[nf][3]);
    }
}

// ===========================================================================
// dense23: reduce split-K partials (4-way ILP) + bias + relu -> h1;
//          h2 = relu(h1 @ d2_w + b2);  theta = h2 @ d3_w + b3.
// ===========================================================================
__global__ void __launch_bounds__(128) dense23_kernel(
    const float* __restrict__ d1b,
    const float* __restrict__ d2w, const float* __restrict__ d2b,
    const float* __restrict__ d3w, const float* __restrict__ d3b)
{
    __shared__ float h1[120];
    __shared__ float h2[84];
    const int b = blockIdx.x, t = threadIdx.x;

    if (t < 120) {
        const float* gp = g_part + (size_t)b*120 + t;
        float s0 = d1b[t], s1 = 0.f, s2 = 0.f, s3 = 0.f;
#pragma unroll 4
        for (int i = 0; i < D1_SPLITS; i += 4) {
            s0 += gp[(size_t)(i+0)*BATCH*120];
            s1 += gp[(size_t)(i+1)*BATCH*120];
            s2 += gp[(size_t)(i+2)*BATCH*120];
            s3 += gp[(size_t)(i+3)*BATCH*120];
        }
        h1[t] = fmaxf((s0 + s1) + (s2 + s3), 0.f);
    }
    __syncthreads();
    if (t < 84) {
        float s = d2b[t];
#pragma unroll 4
        for (int k = 0; k < 120; ++k)
            s = fmaf(h1[k], d2w[k*84 + t], s);
        h2[t] = fmaxf(s, 0.f);
    }
    __syncthreads();
    if (t < 6) {
        float s = d3b[t];
#pragma unroll 4
        for (int k = 0; k < 84; ++k)
            s = fmaf(h2[k], d3w[k*6 + t], s);
        g_theta[b*6 + t] = s;
    }
}

// ===========================================================================
// sampler: affine grid + bilinear sample + 1x1 conv + sigmoid.
// ===========================================================================
__global__ void __launch_bounds__(256) sampler_kernel(
    const float* __restrict__ x, const float* __restrict__ ow,
    const float* __restrict__ ob, float* __restrict__ out)
{
    __shared__ float th[6];
    const int b = blockIdx.y;
    const int h = blockIdx.x;
    const int w = threadIdx.x;
    if (w < 6) th[w] = g_theta[b*6 + w];
    __syncthreads();

    const float gx = (float)w * (2.f/256.f) - 1.f;
    const float gy = (float)h * (2.f/256.f) - 1.f;
    const float px = (th[0]*gx + th[1]*gy + th[2] + 1.f) * 128.f;
    const float py = (th[3]*gx + th[4]*gy + th[5] + 1.f) * 128.f;

    const int fx = (int)floorf(px);
    const int fy = (int)floorf(py);
    const int x1 = min(max(fx,     0), HW-1);
    const int x2 = min(max(fx + 1, 0), HW-1);
    const int y1 = min(max(fy,     0), HW-1);
    const int y2 = min(max(fy + 1, 0), HW-1);

    const float* img = x + (size_t)b * (HW*HW);
    const float p11 = img[y1*HW + x1];
    const float p12 = img[y2*HW + x1];
    const float p21 = img[y1*HW + x2];
    const float p22 = img[y2*HW + x2];

    const float wx1 = (float)x2 - px;
    const float wx2 = px - (float)x1;
    const float wy1 = (float)y2 - py;
    const float wy2 = py - (float)y1;

    const float r = wx1*(wy1*p11 + wy2*p12) + wx2*(wy1*p21 + wy2*p22);
    const float t = r * __ldg(ow) + __ldg(ob);
    out[((size_t)b*HW + h)*HW + w] = 1.f / (1.f + expf(-t));
}

// ===========================================================================
// launch
// ===========================================================================
extern "C" void kernel_launch(void* const* d_in, const int* in_sizes, int n_in,
                              void* d_out, int out_size)
{
    const float* x      = (const float*)d_in[0];
    const float* c1w    = (const float*)d_in[1];
    const float* c1b    = (const float*)d_in[2];
    const float* c2w    = (const float*)d_in[3];
    const float* c2b    = (const float*)d_in[4];
    const float* d1w    = (const float*)d_in[5];
    const float* d1b    = (const float*)d_in[6];
    const float* d2w    = (const float*)d_in[7];
    const float* d2b    = (const float*)d_in[8];
    const float* d3w    = (const float*)d_in[9];
    const float* d3b    = (const float*)d_in[10];
    const float* outw   = (const float*)d_in[11];
    const float* outb   = (const float*)d_in[12];
    float* out = (float*)d_out;

    (void)in_sizes; (void)n_in; (void)out_size;

    cudaFuncSetAttribute(conv2_kernel,
                         cudaFuncAttributeMaxDynamicSharedMemorySize, C2_SMEM_B);

    wprep_kernel<<<25, 256>>>(c2w);
    conv1_kernel<<<dim3(8, 8, BATCH), 256>>>(x, c1w, c1b);
    conv2_kernel<<<dim3(4, 8, BATCH), 256, C2_SMEM_B>>>(c2b);
    dense1_kernel<<<D1_SPLITS, 256>>>(d1w);
    dense23_kernel<<<BATCH, 128>>>(d1b, d2w, d2b, d3w, d3b);
    sampler_kernel<<<dim3(HW, BATCH), 256>>>(x, outw, outb, out);
}

// round 14
// speedup vs baseline: 1.2236x; 1.2236x over previous
#include <cuda_runtime.h>
#include <cuda_fp16.h>
#include <math.h>

// ---------------------------------------------------------------------------
// SpatialTransformerInputHead  (B=128, H=W=256, C=1)
//   conv1 5x5 1->14 + relu + maxpool2  (fp32 f32x2)         -> g_buf1 fp16 NHWC16
//   conv2 5x5 14->32 + relu + maxpool2 (fp16 HMMA, fp32 acc)-> g_buf2 fp16 NHWC
//   dense1 119072->120 (f32x2 split-K, 2-row register blocking)
//   dense 120->84 relu, 84->6 -> theta
//   bilinear grid sample + 1x1 conv + sigmoid -> [128,256,256,1]
// ---------------------------------------------------------------------------

typedef unsigned long long ull;
typedef unsigned int uint32;

#define BATCH 128
#define HW    256
#define P1    126
#define P2    61
#define FLAT  (61*61*32)   // 119072

#define D1_SPLITS 296      // 2 blocks/SM, exactly 1 wave
#define D1_KCHUNK 403      // 296*403 = 119288 >= FLAT

// --------- scratch -----------------------------------------------------------
__device__ __half g_buf1[(size_t)BATCH*P1*P1*16];  // conv1 pooled, NHWC16, fp16
__device__ __half g_w16[25*32*24];                 // conv2 weights fp16 [tap][co][k24]
__device__ __half g_buf2[(size_t)BATCH*FLAT];      // conv2 pooled, NHWC flat, fp16
__device__ float  g_part[(size_t)D1_SPLITS*BATCH*120];
__device__ float  g_theta[BATCH*6];

// --------- helpers -----------------------------------------------------------
__device__ __forceinline__ ull pk2(float v) {
    ull r;
    asm("mov.b64 %0, {%1, %2};" : "=l"(r) : "f"(v), "f"(v));
    return r;
}
__device__ __forceinline__ void upk2(ull v, float& lo, float& hi) {
    asm("mov.b64 {%0, %1}, %2;" : "=f"(lo), "=f"(hi) : "l"(v));
}
#define FMA2(d, a, b) asm("fma.rn.f32x2 %0, %1, %2, %0;" : "+l"(d) : "l"(a), "l"(b))

__device__ __forceinline__ uint32 smem_u32(const void* p) {
    uint32 a;
    asm("{ .reg .u64 t; cvta.to.shared.u64 t, %1; cvt.u32.u64 %0, t; }"
        : "=r"(a) : "l"(p));
    return a;
}

#define MMA_F16(c, a0, a1, a2, a3, b0, b1)                                     \
    asm volatile(                                                              \
        "mma.sync.aligned.m16n8k16.row.col.f32.f16.f16.f32 "                   \
        "{%0,%1,%2,%3}, {%4,%5,%6,%7}, {%8,%9}, {%0,%1,%2,%3};"                \
        : "+f"((c)[0]), "+f"((c)[1]), "+f"((c)[2]), "+f"((c)[3])               \
        : "r"(a0), "r"(a1), "r"(a2), "r"(a3), "r"(b0), "r"(b1))

#define LDSM_X4(r0, r1, r2, r3, addr)                                          \
    asm volatile("ldmatrix.sync.aligned.m8n8.x4.shared.b16 {%0,%1,%2,%3}, [%4];" \
        : "=r"(r0), "=r"(r1), "=r"(r2), "=r"(r3) : "r"(addr))

// ===========================================================================
// wprep: conv2 weights HWIO fp32 -> fp16 [tap][co(32)][ci pad 24], once.
// ===========================================================================
__global__ void __launch_bounds__(256) wprep_kernel(const float* __restrict__ w)
{
    const int tap = blockIdx.x;
    for (int i = threadIdx.x; i < 768; i += 256) {
        int n = i / 24, k = i - n*24;
        float v = (k < 14) ? w[tap*448 + k*32 + n] : 0.f;
        g_w16[tap*768 + i] = __float2half_rn(v);
    }
}

// ===========================================================================
// conv1 (5x5, 1->14) + relu + maxpool2, fp32 f32x2 math, fp16 NHWC16 output.
// grid (8,8,128), 256 threads.
// ===========================================================================
__global__ void __launch_bounds__(256) conv1_kernel(
    const float* __restrict__ x, const float* __restrict__ w,
    const float* __restrict__ bias)
{
    __shared__ __align__(16) float sw[352];
    __shared__ __align__(16) float sb[16];
    __shared__ __align__(16) float sin_[36*36];

    const int b  = blockIdx.z;
    const int ox = blockIdx.x * 32;
    const int oy = blockIdx.y * 32;
    const int tid = threadIdx.x;

    for (int i = tid; i < 350; i += 256) sw[i] = w[i];
    if (tid < 14)  sb[tid] = bias[tid];

    const float* xb = x + (size_t)b * (HW*HW);
    for (int i = tid; i < 36*36; i += 256) {
        int r = i / 36, c = i % 36;
        int gy = oy + r, gx = ox + c;
        sin_[i] = (gy < HW && gx < HW) ? xb[gy*HW + gx] : 0.f;
    }
    __syncthreads();

    const int tx = tid & 15, ty = tid >> 4;

    ull acc[4][7];
#pragma unroll
    for (int p = 0; p < 4; ++p)
#pragma unroll
        for (int j = 0; j < 7; ++j) acc[p][j] = 0ull;

    const float* ib = sin_ + (2*ty)*36 + 2*tx;
#pragma unroll
    for (int dy = 0; dy < 5; ++dy) {
        const float* ra = ib + dy*36;
        const float* rb = ra + 36;
#pragma unroll
        for (int dx = 0; dx < 5; ++dx) {
            ull p00 = pk2(ra[dx]);
            ull p01 = pk2(ra[dx+1]);
            ull p10 = pk2(rb[dx]);
            ull p11 = pk2(rb[dx+1]);
            const ull* wp = (const ull*)&sw[(dy*5 + dx)*14];
#pragma unroll
            for (int j = 0; j < 7; ++j) {
                ull wv = wp[j];
                FMA2(acc[0][j], p00, wv);
                FMA2(acc[1][j], p01, wv);
                FMA2(acc[2][j], p10, wv);
                FMA2(acc[3][j], p11, wv);
            }
        }
    }

    const int x0 = blockIdx.x*16 + tx;
    const int y0 = blockIdx.y*16 + ty;
    if (x0 < P1 && y0 < P1) {
        union { uint4 u[2]; __half2 h2[8]; } pk;
#pragma unroll
        for (int j = 0; j < 7; ++j) {
            float l0,h0,l1,h1,l2,h2,l3,h3;
            upk2(acc[0][j], l0, h0);
            upk2(acc[1][j], l1, h1);
            upk2(acc[2][j], l2, h2);
            upk2(acc[3][j], l3, h3);
            float m0 = fmaxf(fmaxf(l0,l1), fmaxf(l2,l3)) + sb[2*j];
            float m1 = fmaxf(fmaxf(h0,h1), fmaxf(h2,h3)) + sb[2*j+1];
            pk.h2[j] = __float22half2_rn(make_float2(fmaxf(m0, 0.f), fmaxf(m1, 0.f)));
        }
        pk.h2[7] = __float22half2_rn(make_float2(0.f, 0.f));
        uint4* dst = (uint4*)(g_buf1 + ((size_t)(b*P1 + y0)*P1 + x0)*16);
        dst[0] = pk.u[0];
        dst[1] = pk.u[1];
    }
}

// ===========================================================================
// conv2 via fp16 mma.sync m16n8k16 (fp32 accum): 5x5 conv = 25 shifted GEMMs.
// Block: 8x16 pooled, 256 threads (8 warps), 2 blocks/SM.
// Epilogue: 2x2 maxpool + bias + relu -> fp16 NHWC flat g_buf2.
// ===========================================================================
#define C2_A_B    (720*48)                  // 34560 B (20 rows x 36 cols)
#define C2_W_B    (25*32*48)                // 38400 B
#define C2_SMEM_B (C2_A_B + C2_W_B + 128)   // 73088 B

__global__ void __launch_bounds__(256, 2) conv2_kernel(const float* __restrict__ bias)
{
    extern __shared__ __align__(16) unsigned char smem[];
    __half* At = (__half*)smem;                        // [pos 20x36][24]
    __half* Wt = (__half*)(smem + C2_A_B);             // [tap][co32][24]
    float*  sb = (float*)(smem + C2_A_B + C2_W_B);     // [32]

    const int b   = blockIdx.z;
    const int px0 = blockIdx.x * 16;
    const int py0 = blockIdx.y * 8;
    const int ix0 = px0 * 2;
    const int iy0 = py0 * 2;
    const int tid = threadIdx.x;

    // W: straight 38.4KB vector copy from preconverted fp16
    {
        const uint4* ws = (const uint4*)g_w16;
        uint4* wd = (uint4*)Wt;
        for (int i = tid; i < C2_W_B/16; i += 256) wd[i] = ws[i];
    }
    if (tid < 32) sb[tid] = bias[tid];

    // A tile: 20x36 positions, 32B fp16 copy + 16B zero pad (48B rows)
    for (int p = tid; p < 720; p += 256) {
        int r = p / 36, c = p - r*36;
        int gy = iy0 + r, gx = ix0 + c;
        uint4 u0 = make_uint4(0,0,0,0), u1 = u0;
        if (gy < P1 && gx < P1) {
            const uint4* s4 = (const uint4*)(g_buf1 + ((size_t)(b*P1 + gy)*P1 + gx)*16);
            u0 = s4[0]; u1 = s4[1];
        }
        uint4* d = (uint4*)(At + p*24);
        d[0] = u0; d[1] = u1; d[2] = make_uint4(0,0,0,0);
    }
    __syncthreads();

    const int warp = tid >> 5, lane = tid & 31;
    const int y0 = 2 * warp;
    const uint32 atb = smem_u32(At);
    const uint32 wtb = smem_u32(Wt);

    const uint32 aoff = (uint32)((lane & 15)*48 + (lane >> 4)*16);
    const uint32 boff = (uint32)(((lane & 7) + ((lane >> 4) & 1)*8)*48
                                 + ((lane >> 3) & 1)*16);

    float cacc[2][2][4][4];
#pragma unroll
    for (int s = 0; s < 2; ++s)
#pragma unroll
        for (int xh = 0; xh < 2; ++xh)
#pragma unroll
            for (int nf = 0; nf < 4; ++nf)
#pragma unroll
                for (int k = 0; k < 4; ++k) cacc[s][xh][nf][k] = 0.f;

#pragma unroll 1
    for (int tap = 0; tap < 25; ++tap) {
        const int dy = tap / 5, dx = tap - 5*dy;

        const uint32 wb = wtb + (uint32)(tap*1536) + boff;
        uint32 b00, b01, b10, b11, b20, b21, b30, b31;
        LDSM_X4(b00, b01, b10, b11, wb);
        LDSM_X4(b20, b21, b30, b31, wb + 768);

#pragma unroll
        for (int s = 0; s < 2; ++s) {
            const int rowbase = (y0 + s + dy)*36 + dx;
#pragma unroll
            for (int xh = 0; xh < 2; ++xh) {
                uint32 a0, a1, a2, a3;
                LDSM_X4(a0, a1, a2, a3,
                        atb + (uint32)((rowbase + xh*16)*48) + aoff);
                MMA_F16(cacc[s][xh][0], a0, a1, a2, a3, b00, b01);
                MMA_F16(cacc[s][xh][1], a0, a1, a2, a3, b10, b11);
                MMA_F16(cacc[s][xh][2], a0, a1, a2, a3, b20, b21);
                MMA_F16(cacc[s][xh][3], a0, a1, a2, a3, b30, b31);
            }
        }
    }

    // epilogue: 2x2 maxpool + bias + relu -> fp16 NHWC
    const int py = py0 + warp;
    const int r  = lane >> 2;
    const bool active = ((r & 1) == 0);
    const int j = r >> 1;
    const int n0 = (lane & 3) * 2;

#pragma unroll
    for (int xh = 0; xh < 2; ++xh)
#pragma unroll
    for (int nf = 0; nf < 4; ++nf) {
        float m0 = fmaxf(cacc[0][xh][nf][0], cacc[1][xh][nf][0]);
        float m1 = fmaxf(cacc[0][xh][nf][1], cacc[1][xh][nf][1]);
        float m2 = fmaxf(cacc[0][xh][nf][2], cacc[1][xh][nf][2]);
        float m3 = fmaxf(cacc[0][xh][nf][3], cacc[1][xh][nf][3]);
        float o0 = fmaxf(m0, __shfl_down_sync(0xffffffffu, m0, 4));
        float o1 = fmaxf(m1, __shfl_down_sync(0xffffffffu, m1, 4));
        float o2 = fmaxf(m2, __shfl_down_sync(0xffffffffu, m2, 4));
        float o3 = fmaxf(m3, __shfl_down_sync(0xffffffffu, m3, 4));
        if (active && py < P2) {
            const int ch  = nf*8 + n0;
            const float b0v = sb[ch], b1v = sb[ch+1];
            const int pxa = px0 + xh*8 + j;
            const int pxb = pxa + 4;
            if (pxa < P2) {
                __half2 v = __float22half2_rn(
                    make_float2(fmaxf(o0 + b0v, 0.f), fmaxf(o1 + b1v, 0.f)));
                *(__half2*)(g_buf2 + (((size_t)b*P2 + py)*P2 + pxa)*32 + ch) = v;
            }
            if (pxb < P2) {
                __half2 v = __float22half2_rn(
                    make_float2(fmaxf(o2 + b0v, 0.f), fmaxf(o3 + b1v, 0.f)));
                *(__half2*)(g_buf2 + (((size_t)b*P2 + py)*P2 + pxb)*32 + ch) = v;
            }
        }
    }
}

// ===========================================================================
// dense1 split-K GEMM: [128 x 119072](fp16) @ [119072 x 120] -> fp32 partials.
// grid 296 blocks (2/SM, one wave), 256 threads, 2 blocks/SM.
// Each thread: 2 batch rows x 30 outputs (30 ull accumulators).
// Per k-step: 1 LDS.64 (row-pair) + 15 broadcast LDS.64 (W) -> 30 FMA2.
// ===========================================================================
__global__ void __launch_bounds__(256, 2) dense1_kernel(const float* __restrict__ w)
{
    __shared__ __align__(16) float As[32*134];   // [kk][row(128) pad 134]
    __shared__ __align__(16) float Ws[32*120];   // [kk][120]

    const int k0   = blockIdx.x * D1_KCHUNK;
    const int kend = min(k0 + D1_KCHUNK, FLAT);
    const int tid  = threadIdx.x;
    const int rp   = tid & 63;          // row pair: rows 2rp, 2rp+1
    const int g    = tid >> 6;          // 0..3 -> 30 output cols each

    ull acc0[15], acc1[15];
#pragma unroll
    for (int j = 0; j < 15; ++j) { acc0[j] = 0ull; acc1[j] = 0ull; }

    for (int kb = k0; kb < kend; kb += 32) {
        for (int i = tid; i < 128*32; i += 256) {
            int r  = i >> 5;
            int kk = i & 31;
            int k  = kb + kk;
            As[kk*134 + r] = (k < kend)
                ? __half2float(g_buf2[(size_t)r*FLAT + k]) : 0.f;
        }
        for (int i = tid; i < 32*120; i += 256) {
            int kk = i / 120, oo = i - kk*120;
            int k = kb + kk;
            Ws[i] = (k < kend) ? w[(size_t)k*120 + oo] : 0.f;
        }
        __syncthreads();
#pragma unroll
        for (int kk = 0; kk < 32; ++kk) {
            const float2 a2 = *(const float2*)&As[kk*134 + 2*rp];
            ull a0 = pk2(a2.x);
            ull a1 = pk2(a2.y);
            const ull* wsp = (const ull*)&Ws[kk*120 + g*30];
#pragma unroll
            for (int j = 0; j < 15; ++j) {
                ull wv = wsp[j];
                FMA2(acc0[j], a0, wv);
                FMA2(acc1[j], a1, wv);
            }
        }
        __syncthreads();
    }

    float* p0 = g_part + ((size_t)blockIdx.x*BATCH + 2*rp)*120 + g*30;
    float* p1 = p0 + 120;
#pragma unroll
    for (int j = 0; j < 15; ++j) {
        *(ull*)(p0 + 2*j) = acc0[j];
        *(ull*)(p1 + 2*j) = acc1[j];
    }
}

// ===========================================================================
// dense23: reduce split-K partials (4-way ILP) + bias + relu -> h1;
//          h2 = relu(h1 @ d2_w + b2);  theta = h2 @ d3_w + b3.
// ===========================================================================
__global__ void __launch_bounds__(128) dense23_kernel(
    const float* __restrict__ d1b,
    const float* __restrict__ d2w, const float* __restrict__ d2b,
    const float* __restrict__ d3w, const float* __restrict__ d3b)
{
    __shared__ float h1[120];
    __shared__ float h2[84];
    const int b = blockIdx.x, t = threadIdx.x;

    if (t < 120) {
        const float* gp = g_part + (size_t)b*120 + t;
        float s0 = d1b[t], s1 = 0.f, s2 = 0.f, s3 = 0.f;
#pragma unroll 4
        for (int i = 0; i < D1_SPLITS; i += 4) {
            s0 += gp[(size_t)(i+0)*BATCH*120];
            s1 += gp[(size_t)(i+1)*BATCH*120];
            s2 += gp[(size_t)(i+2)*BATCH*120];
            s3 += gp[(size_t)(i+3)*BATCH*120];
        }
        h1[t] = fmaxf((s0 + s1) + (s2 + s3), 0.f);
    }
    __syncthreads();
    if (t < 84) {
        float s = d2b[t];
#pragma unroll 4
        for (int k = 0; k < 120; ++k)
            s = fmaf(h1[k], d2w[k*84 + t], s);
        h2[t] = fmaxf(s, 0.f);
    }
    __syncthreads();
    if (t < 6) {
        float s = d3b[t];
#pragma unroll 4
        for (int k = 0; k < 84; ++k)
            s = fmaf(h2[k], d3w[k*6 + t], s);
        g_theta[b*6 + t] = s;
    }
}

// ===========================================================================
// sampler: affine grid + bilinear sample + 1x1 conv + sigmoid.
// ===========================================================================
__global__ void __launch_bounds__(256) sampler_kernel(
    const float* __restrict__ x, const float* __restrict__ ow,
    const float* __restrict__ ob, float* __restrict__ out)
{
    __shared__ float th[6];
    const int b = blockIdx.y;
    const int h = blockIdx.x;
    const int w = threadIdx.x;
    if (w < 6) th[w] = g_theta[b*6 + w];
    __syncthreads();

    const float gx = (float)w * (2.f/256.f) - 1.f;
    const float gy = (float)h * (2.f/256.f) - 1.f;
    const float px = (th[0]*gx + th[1]*gy + th[2] + 1.f) * 128.f;
    const float py = (th[3]*gx + th[4]*gy + th[5] + 1.f) * 128.f;

    const int fx = (int)floorf(px);
    const int fy = (int)floorf(py);
    const int x1 = min(max(fx,     0), HW-1);
    const int x2 = min(max(fx + 1, 0), HW-1);
    const int y1 = min(max(fy,     0), HW-1);
    const int y2 = min(max(fy + 1, 0), HW-1);

    const float* img = x + (size_t)b * (HW*HW);
    const float p11 = img[y1*HW + x1];
    const float p12 = img[y2*HW + x1];
    const float p21 = img[y1*HW + x2];
    const float p22 = img[y2*HW + x2];

    const float wx1 = (float)x2 - px;
    const float wx2 = px - (float)x1;
    const float wy1 = (float)y2 - py;
    const float wy2 = py - (float)y1;

    const float r = wx1*(wy1*p11 + wy2*p12) + wx2*(wy1*p21 + wy2*p22);
    const float t = r * __ldg(ow) + __ldg(ob);
    out[((size_t)b*HW + h)*HW + w] = 1.f / (1.f + expf(-t));
}

// ===========================================================================
// launch
// ===========================================================================
extern "C" void kernel_launch(void* const* d_in, const int* in_sizes, int n_in,
                              void* d_out, int out_size)
{
    const float* x      = (const float*)d_in[0];
    const float* c1w    = (const float*)d_in[1];
    const float* c1b    = (const float*)d_in[2];
    const float* c2w    = (const float*)d_in[3];
    const float* c2b    = (const float*)d_in[4];
    const float* d1w    = (const float*)d_in[5];
    const float* d1b    = (const float*)d_in[6];
    const float* d2w    = (const float*)d_in[7];
    const float* d2b    = (const float*)d_in[8];
    const float* d3w    = (const float*)d_in[9];
    const float* d3b    = (const float*)d_in[10];
    const float* outw   = (const float*)d_in[11];
    const float* outb   = (const float*)d_in[12];
    float* out = (float*)d_out;

    (void)in_sizes; (void)n_in; (void)out_size;

    cudaFuncSetAttribute(conv2_kernel,
                         cudaFuncAttributeMaxDynamicSharedMemorySize, C2_SMEM_B);

    wprep_kernel<<<25, 256>>>(c2w);
    conv1_kernel<<<dim3(8, 8, BATCH), 256>>>(x, c1w, c1b);
    conv2_kernel<<<dim3(4, 8, BATCH), 256, C2_SMEM_B>>>(c2b);
    dense1_kernel<<<D1_SPLITS, 256>>>(d1w);
    dense23_kernel<<<BATCH, 128>>>(d1b, d2w, d2b, d3w, d3b);
    sampler_kernel<<<dim3(HW, BATCH), 256>>>(x, outw, outb, out);
}

// round 15
// speedup vs baseline: 1.2732x; 1.0406x over previous
#include <cuda_runtime.h>
#include <cuda_fp16.h>
#include <math.h>

// ---------------------------------------------------------------------------
// SpatialTransformerInputHead  (B=128, H=W=256, C=1)
//   conv1 5x5 1->14 + relu + maxpool2  (fp32 f32x2)         -> g_buf1 fp16 NHWC16
//   conv2 5x5 14->32 + relu + maxpool2 (fp16 HMMA, fp32 acc)-> g_buf2 fp16 NHWC
//   dense1 119072->120 (f32x2 split-K, 4-row register blocking)
//   dense 120->84 relu, 84->6 -> theta
//   bilinear grid sample + 1x1 conv + sigmoid -> [128,256,256,1]
// ---------------------------------------------------------------------------

typedef unsigned long long ull;
typedef unsigned int uint32;

#define BATCH 128
#define HW    256
#define P1    126
#define P2    61
#define FLAT  (61*61*32)   // 119072

#define D1_SPLITS 296      // 2 blocks/SM, one wave
#define D1_KCHUNK 408      // mult of 8 (16B-aligned vector loads); 296*408 >= FLAT

// --------- scratch -----------------------------------------------------------
__device__ __half g_buf1[(size_t)BATCH*P1*P1*16];  // conv1 pooled, NHWC16, fp16
__device__ __half g_w16[25*32*24];                 // conv2 weights fp16 [tap][co][k24]
__device__ __half g_buf2[(size_t)BATCH*FLAT];      // conv2 pooled, NHWC flat, fp16
__device__ float  g_part[(size_t)D1_SPLITS*BATCH*128];  // padded n-stride 128
__device__ float  g_red[8*BATCH*120];
__device__ float  g_theta[BATCH*6];

// --------- helpers -----------------------------------------------------------
__device__ __forceinline__ ull pk2(float v) {
    ull r;
    asm("mov.b64 %0, {%1, %2};" : "=l"(r) : "f"(v), "f"(v));
    return r;
}
__device__ __forceinline__ void upk2(ull v, float& lo, float& hi) {
    asm("mov.b64 {%0, %1}, %2;" : "=f"(lo), "=f"(hi) : "l"(v));
}
#define FMA2(d, a, b) asm("fma.rn.f32x2 %0, %1, %2, %0;" : "+l"(d) : "l"(a), "l"(b))

__device__ __forceinline__ uint32 smem_u32(const void* p) {
    uint32 a;
    asm("{ .reg .u64 t; cvta.to.shared.u64 t, %1; cvt.u32.u64 %0, t; }"
        : "=r"(a) : "l"(p));
    return a;
}

#define MMA_F16(c, a0, a1, a2, a3, b0, b1)                                     \
    asm volatile(                                                              \
        "mma.sync.aligned.m16n8k16.row.col.f32.f16.f16.f32 "                   \
        "{%0,%1,%2,%3}, {%4,%5,%6,%7}, {%8,%9}, {%0,%1,%2,%3};"                \
        : "+f"((c)[0]), "+f"((c)[1]), "+f"((c)[2]), "+f"((c)[3])               \
        : "r"(a0), "r"(a1), "r"(a2), "r"(a3), "r"(b0), "r"(b1))

#define LDSM_X4(r0, r1, r2, r3, addr)                                          \
    asm volatile("ldmatrix.sync.aligned.m8n8.x4.shared.b16 {%0,%1,%2,%3}, [%4];" \
        : "=r"(r0), "=r"(r1), "=r"(r2), "=r"(r3) : "r"(addr))

// ===========================================================================
// wprep: conv2 weights HWIO fp32 -> fp16 [tap][co(32)][ci pad 24], once.
// ===========================================================================
__global__ void __launch_bounds__(256) wprep_kernel(const float* __restrict__ w)
{
    const int tap = blockIdx.x;
    for (int i = threadIdx.x; i < 768; i += 256) {
        int n = i / 24, k = i - n*24;
        float v = (k < 14) ? w[tap*448 + k*32 + n] : 0.f;
        g_w16[tap*768 + i] = __float2half_rn(v);
    }
}

// ===========================================================================
// conv1 (5x5, 1->14) + relu + maxpool2, fp32 f32x2 math, fp16 NHWC16 output.
// grid (8,8,128), 256 threads.
// ===========================================================================
__global__ void __launch_bounds__(256) conv1_kernel(
    const float* __restrict__ x, const float* __restrict__ w,
    const float* __restrict__ bias)
{
    __shared__ __align__(16) float sw[352];
    __shared__ __align__(16) float sb[16];
    __shared__ __align__(16) float sin_[36*36];

    const int b  = blockIdx.z;
    const int ox = blockIdx.x * 32;
    const int oy = blockIdx.y * 32;
    const int tid = threadIdx.x;

    for (int i = tid; i < 350; i += 256) sw[i] = w[i];
    if (tid < 14)  sb[tid] = bias[tid];

    const float* xb = x + (size_t)b * (HW*HW);
    for (int i = tid; i < 36*36; i += 256) {
        int r = i / 36, c = i % 36;
        int gy = oy + r, gx = ox + c;
        sin_[i] = (gy < HW && gx < HW) ? xb[gy*HW + gx] : 0.f;
    }
    __syncthreads();

    const int tx = tid & 15, ty = tid >> 4;

    ull acc[4][7];
#pragma unroll
    for (int p = 0; p < 4; ++p)
#pragma unroll
        for (int j = 0; j < 7; ++j) acc[p][j] = 0ull;

    const float* ib = sin_ + (2*ty)*36 + 2*tx;
#pragma unroll
    for (int dy = 0; dy < 5; ++dy) {
        const float* ra = ib + dy*36;
        const float* rb = ra + 36;
#pragma unroll
        for (int dx = 0; dx < 5; ++dx) {
            ull p00 = pk2(ra[dx]);
            ull p01 = pk2(ra[dx+1]);
            ull p10 = pk2(rb[dx]);
            ull p11 = pk2(rb[dx+1]);
            const ull* wp = (const ull*)&sw[(dy*5 + dx)*14];
#pragma unroll
            for (int j = 0; j < 7; ++j) {
                ull wv = wp[j];
                FMA2(acc[0][j], p00, wv);
                FMA2(acc[1][j], p01, wv);
                FMA2(acc[2][j], p10, wv);
                FMA2(acc[3][j], p11, wv);
            }
        }
    }

    const int x0 = blockIdx.x*16 + tx;
    const int y0 = blockIdx.y*16 + ty;
    if (x0 < P1 && y0 < P1) {
        union { uint4 u[2]; __half2 h2[8]; } pk;
#pragma unroll
        for (int j = 0; j < 7; ++j) {
            float l0,h0,l1,h1,l2,h2,l3,h3;
            upk2(acc[0][j], l0, h0);
            upk2(acc[1][j], l1, h1);
            upk2(acc[2][j], l2, h2);
            upk2(acc[3][j], l3, h3);
            float m0 = fmaxf(fmaxf(l0,l1), fmaxf(l2,l3)) + sb[2*j];
            float m1 = fmaxf(fmaxf(h0,h1), fmaxf(h2,h3)) + sb[2*j+1];
            pk.h2[j] = __float22half2_rn(make_float2(fmaxf(m0, 0.f), fmaxf(m1, 0.f)));
        }
        pk.h2[7] = __float22half2_rn(make_float2(0.f, 0.f));
        uint4* dst = (uint4*)(g_buf1 + ((size_t)(b*P1 + y0)*P1 + x0)*16);
        dst[0] = pk.u[0];
        dst[1] = pk.u[1];
    }
}

// ===========================================================================
// conv2 via fp16 mma.sync m16n8k16 (fp32 accum): 5x5 conv = 25 shifted GEMMs.
// Block: 8x16 pooled, 256 threads (8 warps), 2 blocks/SM.
// Epilogue: 2x2 maxpool + bias + relu -> fp16 NHWC flat g_buf2.
// ===========================================================================
#define C2_A_B    (720*48)                  // 34560 B (20 rows x 36 cols)
#define C2_W_B    (25*32*48)                // 38400 B
#define C2_SMEM_B (C2_A_B + C2_W_B + 128)   // 73088 B

__global__ void __launch_bounds__(256, 2) conv2_kernel(const float* __restrict__ bias)
{
    extern __shared__ __align__(16) unsigned char smem[];
    __half* At = (__half*)smem;                        // [pos 20x36][24]
    __half* Wt = (__half*)(smem + C2_A_B);             // [tap][co32][24]
    float*  sb = (float*)(smem + C2_A_B + C2_W_B);     // [32]

    const int b   = blockIdx.z;
    const int px0 = blockIdx.x * 16;
    const int py0 = blockIdx.y * 8;
    const int ix0 = px0 * 2;
    const int iy0 = py0 * 2;
    const int tid = threadIdx.x;

    // W: straight 38.4KB vector copy from preconverted fp16
    {
        const uint4* ws = (const uint4*)g_w16;
        uint4* wd = (uint4*)Wt;
        for (int i = tid; i < C2_W_B/16; i += 256) wd[i] = ws[i];
    }
    if (tid < 32) sb[tid] = bias[tid];

    // A tile: 20x36 positions, 32B fp16 copy + 16B zero pad (48B rows)
    for (int p = tid; p < 720; p += 256) {
        int r = p / 36, c = p - r*36;
        int gy = iy0 + r, gx = ix0 + c;
        uint4 u0 = make_uint4(0,0,0,0), u1 = u0;
        if (gy < P1 && gx < P1) {
            const uint4* s4 = (const uint4*)(g_buf1 + ((size_t)(b*P1 + gy)*P1 + gx)*16);
            u0 = s4[0]; u1 = s4[1];
        }
        uint4* d = (uint4*)(At + p*24);
        d[0] = u0; d[1] = u1; d[2] = make_uint4(0,0,0,0);
    }
    __syncthreads();

    const int warp = tid >> 5, lane = tid & 31;
    const int y0 = 2 * warp;
    const uint32 atb = smem_u32(At);
    const uint32 wtb = smem_u32(Wt);

    const uint32 aoff = (uint32)((lane & 15)*48 + (lane >> 4)*16);
    const uint32 boff = (uint32)(((lane & 7) + ((lane >> 4) & 1)*8)*48
                                 + ((lane >> 3) & 1)*16);

    float cacc[2][2][4][4];
#pragma unroll
    for (int s = 0; s < 2; ++s)
#pragma unroll
        for (int xh = 0; xh < 2; ++xh)
#pragma unroll
            for (int nf = 0; nf < 4; ++nf)
#pragma unroll
                for (int k = 0; k < 4; ++k) cacc[s][xh][nf][k] = 0.f;

#pragma unroll 1
    for (int tap = 0; tap < 25; ++tap) {
        const int dy = tap / 5, dx = tap - 5*dy;

        const uint32 wb = wtb + (uint32)(tap*1536) + boff;
        uint32 b00, b01, b10, b11, b20, b21, b30, b31;
        LDSM_X4(b00, b01, b10, b11, wb);
        LDSM_X4(b20, b21, b30, b31, wb + 768);

#pragma unroll
        for (int s = 0; s < 2; ++s) {
            const int rowbase = (y0 + s + dy)*36 + dx;
#pragma unroll
            for (int xh = 0; xh < 2; ++xh) {
                uint32 a0, a1, a2, a3;
                LDSM_X4(a0, a1, a2, a3,
                        atb + (uint32)((rowbase + xh*16)*48) + aoff);
                MMA_F16(cacc[s][xh][0], a0, a1, a2, a3, b00, b01);
                MMA_F16(cacc[s][xh][1], a0, a1, a2, a3, b10, b11);
                MMA_F16(cacc[s][xh][2], a0, a1, a2, a3, b20, b21);
                MMA_F16(cacc[s][xh][3], a0, a1, a2, a3, b30, b31);
            }
        }
    }

    // epilogue: 2x2 maxpool + bias + relu -> fp16 NHWC
    const int py = py0 + warp;
    const int r  = lane >> 2;
    const bool active = ((r & 1) == 0);
    const int j = r >> 1;
    const int n0 = (lane & 3) * 2;

#pragma unroll
    for (int xh = 0; xh < 2; ++xh)
#pragma unroll
    for (int nf = 0; nf < 4; ++nf) {
        float m0 = fmaxf(cacc[0][xh][nf][0], cacc[1][xh][nf][0]);
        float m1 = fmaxf(cacc[0][xh][nf][1], cacc[1][xh][nf][1]);
        float m2 = fmaxf(cacc[0][xh][nf][2], cacc[1][xh][nf][2]);
        float m3 = fmaxf(cacc[0][xh][nf][3], cacc[1][xh][nf][3]);
        float o0 = fmaxf(m0, __shfl_down_sync(0xffffffffu, m0, 4));
        float o1 = fmaxf(m1, __shfl_down_sync(0xffffffffu, m1, 4));
        float o2 = fmaxf(m2, __shfl_down_sync(0xffffffffu, m2, 4));
        float o3 = fmaxf(m3, __shfl_down_sync(0xffffffffu, m3, 4));
        if (active && py < P2) {
            const int ch  = nf*8 + n0;
            const float b0v = sb[ch], b1v = sb[ch+1];
            const int pxa = px0 + xh*8 + j;
            const int pxb = pxa + 4;
            if (pxa < P2) {
                __half2 v = __float22half2_rn(
                    make_float2(fmaxf(o0 + b0v, 0.f), fmaxf(o1 + b1v, 0.f)));
                *(__half2*)(g_buf2 + (((size_t)b*P2 + py)*P2 + pxa)*32 + ch) = v;
            }
            if (pxb < P2) {
                __half2 v = __float22half2_rn(
                    make_float2(fmaxf(o2 + b0v, 0.f), fmaxf(o3 + b1v, 0.f)));
                *(__half2*)(g_buf2 + (((size_t)b*P2 + py)*P2 + pxb)*32 + ch) = v;
            }
        }
    }
}

// ===========================================================================
// dense1 split-K GEMM: [128 x 119072](fp16) @ [119072 x 120] -> fp32 partials.
// grid 296 blocks (2/SM, one wave), 256 threads.
// Each thread: 4 batch rows x 16 outputs (warp = output group -> W broadcast).
// Per k-step: 1 LDS.128 (4 rows) + 8 broadcast LDS.64 (W) -> 32 FMA2.
// A-fill: vectorized uint4 loads of 8 fp16; lanes write consecutive rows
// (conflict-free STS).  Ws padded to 128 cols.
// ===========================================================================
__global__ void __launch_bounds__(256, 2) dense1_kernel(const float* __restrict__ w)
{
    __shared__ __align__(16) float As[32*132];   // [kk][row(128) pad 132]
    __shared__ __align__(16) float Ws[32*128];   // [kk][128 (120 real)]

    const int k0   = blockIdx.x * D1_KCHUNK;
    const int kend = min(k0 + D1_KCHUNK, FLAT);
    const int tid  = threadIdx.x;
    const int rp   = tid & 31;          // rows 4rp..4rp+3
    const int g    = tid >> 5;          // warp id = output group (16 cols)

    ull acc[4][8];
#pragma unroll
    for (int rr = 0; rr < 4; ++rr)
#pragma unroll
        for (int j = 0; j < 8; ++j) acc[rr][j] = 0ull;

    for (int kb = k0; kb < kend; kb += 32) {
        // A: 128 rows x 32 halfs; i -> (r = i&127, q = i>>7), k = kb + q*8
        for (int i = tid; i < 512; i += 256) {
            int r = i & 127, q = i >> 7;
            int k = kb + q*8;
            float f0=0,f1=0,f2=0,f3=0,f4=0,f5=0,f6=0,f7=0;
            if (k < kend) {   // k, kend both mult of 8 -> full vector valid
                uint4 v = *(const uint4*)(g_buf2 + (size_t)r*FLAT + k);
                const __half2* h = (const __half2*)&v;
                float2 p0 = __half22float2(h[0]);
                float2 p1 = __half22float2(h[1]);
                float2 p2 = __half22float2(h[2]);
                float2 p3 = __half22float2(h[3]);
                f0=p0.x; f1=p0.y; f2=p1.x; f3=p1.y;
                f4=p2.x; f5=p2.y; f6=p3.x; f7=p3.y;
            }
            float* a = As + (q*8)*132 + r;
            a[0]     = f0; a[132]   = f1; a[264]   = f2; a[396]   = f3;
            a[528]   = f4; a[660]   = f5; a[792]   = f6; a[924]   = f7;
        }
        // W: [kk][128 pad], coalesced along n
        for (int i = tid; i < 4096; i += 256) {
            int kk = i >> 7, oo = i & 127;
            int k = kb + kk;
            Ws[i] = (oo < 120 && k < kend) ? w[(size_t)k*120 + oo] : 0.f;
        }
        __syncthreads();
#pragma unroll
        for (int kk = 0; kk < 32; ++kk) {
            const float4 a4 = *(const float4*)&As[kk*132 + 4*rp];
            ull a0 = pk2(a4.x), a1 = pk2(a4.y), a2 = pk2(a4.z), a3 = pk2(a4.w);
            const ull* wsp = (const ull*)&Ws[kk*128 + g*16];
#pragma unroll
            for (int j = 0; j < 8; ++j) {
                ull wv = wsp[j];
                FMA2(acc[0][j], a0, wv);
                FMA2(acc[1][j], a1, wv);
                FMA2(acc[2][j], a2, wv);
                FMA2(acc[3][j], a3, wv);
            }
        }
        __syncthreads();
    }

    float* p = g_part + ((size_t)blockIdx.x*BATCH + 4*rp)*128 + g*16;
#pragma unroll
    for (int rr = 0; rr < 4; ++rr)
#pragma unroll
        for (int j = 0; j < 8; ++j)
            *(ull*)(p + (size_t)rr*128 + 2*j) = acc[rr][j];
}

// ===========================================================================
// dense1red: stage-1 reduction of 296 splits in 8 chunks of 37.
// grid (8, 128), 128 threads.
// ===========================================================================
__global__ void __launch_bounds__(128) dense1red_kernel()
{
    const int c = blockIdx.x;          // chunk 0..7
    const int b = blockIdx.y;
    const int t = threadIdx.x;
    if (t >= 120) return;

    const size_t stride = (size_t)BATCH * 128;
    const float* gp = g_part + ((size_t)(c*37)*BATCH + b)*128 + t;

    float s0 = 0.f, s1 = 0.f, s2 = 0.f, s3 = 0.f;
#pragma unroll 3
    for (int i = 0; i < 36; i += 4) {
        s0 += gp[(size_t)(i+0)*stride];
        s1 += gp[(size_t)(i+1)*stride];
        s2 += gp[(size_t)(i+2)*stride];
        s3 += gp[(size_t)(i+3)*stride];
    }
    s0 += gp[(size_t)36*stride];
    g_red[((size_t)c*BATCH + b)*120 + t] = (s0 + s1) + (s2 + s3);
}

// ===========================================================================
// dense23: reduce 8 stage-1 partials + bias + relu -> h1;
//          h2 = relu(h1 @ d2_w + b2);  theta = h2 @ d3_w + b3.
// ===========================================================================
__global__ void __launch_bounds__(128) dense23_kernel(
    const float* __restrict__ d1b,
    const float* __restrict__ d2w, const float* __restrict__ d2b,
    const float* __restrict__ d3w, const float* __restrict__ d3b)
{
    __shared__ float h1[120];
    __shared__ float h2[84];
    const int b = blockIdx.x, t = threadIdx.x;

    if (t < 120) {
        const float* gp = g_red + (size_t)b*120 + t;
        float s = d1b[t];
#pragma unroll
        for (int i = 0; i < 8; ++i)
            s += gp[(size_t)i*BATCH*120];
        h1[t] = fmaxf(s, 0.f);
    }
    __syncthreads();
    if (t < 84) {
        float s = d2b[t];
#pragma unroll 4
        for (int k = 0; k < 120; ++k)
            s = fmaf(h1[k], d2w[k*84 + t], s);
        h2[t] = fmaxf(s, 0.f);
    }
    __syncthreads();
    if (t < 6) {
        float s = d3b[t];
#pragma unroll 4
        for (int k = 0; k < 84; ++k)
            s = fmaf(h2[k], d3w[k*6 + t], s);
        g_theta[b*6 + t] = s;
    }
}

// ===========================================================================
// sampler: affine grid + bilinear sample + 1x1 conv + sigmoid.
// ===========================================================================
__global__ void __launch_bounds__(256) sampler_kernel(
    const float* __restrict__ x, const float* __restrict__ ow,
    const float* __restrict__ ob, float* __restrict__ out)
{
    __shared__ float th[6];
    const int b = blockIdx.y;
    const int h = blockIdx.x;
    const int w = threadIdx.x;
    if (w < 6) th[w] = g_theta[b*6 + w];
    __syncthreads();

    const float gx = (float)w * (2.f/256.f) - 1.f;
    const float gy = (float)h * (2.f/256.f) - 1.f;
    const float px = (th[0]*gx + th[1]*gy + th[2] + 1.f) * 128.f;
    const float py = (th[3]*gx + th[4]*gy + th[5] + 1.f) * 128.f;

    const int fx = (int)floorf(px);
    const int fy = (int)floorf(py);
    const int x1 = min(max(fx,     0), HW-1);
    const int x2 = min(max(fx + 1, 0), HW-1);
    const int y1 = min(max(fy,     0), HW-1);
    const int y2 = min(max(fy + 1, 0), HW-1);

    const float* img = x + (size_t)b * (HW*HW);
    const float p11 = img[y1*HW + x1];
    const float p12 = img[y2*HW + x1];
    const float p21 = img[y1*HW + x2];
    const float p22 = img[y2*HW + x2];

    const float wx1 = (float)x2 - px;
    const float wx2 = px - (float)x1;
    const float wy1 = (float)y2 - py;
    const float wy2 = py - (float)y1;

    const float r = wx1*(wy1*p11 + wy2*p12) + wx2*(wy1*p21 + wy2*p22);
    const float t = r * __ldg(ow) + __ldg(ob);
    out[((size_t)b*HW + h)*HW + w] = 1.f / (1.f + expf(-t));
}

// ===========================================================================
// launch
// ===========================================================================
extern "C" void kernel_launch(void* const* d_in, const int* in_sizes, int n_in,
                              void* d_out, int out_size)
{
    const float* x      = (const float*)d_in[0];
    const float* c1w    = (const float*)d_in[1];
    const float* c1b    = (const float*)d_in[2];
    const float* c2w    = (const float*)d_in[3];
    const float* c2b    = (const float*)d_in[4];
    const float* d1w    = (const float*)d_in[5];
    const float* d1b    = (const float*)d_in[6];
    const float* d2w    = (const float*)d_in[7];
    const float* d2b    = (const float*)d_in[8];
    const float* d3w    = (const float*)d_in[9];
    const float* d3b    = (const float*)d_in[10];
    const float* outw   = (const float*)d_in[11];
    const float* outb   = (const float*)d_in[12];
    float* out = (float*)d_out;

    (void)in_sizes; (void)n_in; (void)out_size;

    cudaFuncSetAttribute(conv2_kernel,
                         cudaFuncAttributeMaxDynamicSharedMemorySize, C2_SMEM_B);

    wprep_kernel<<<25, 256>>>(c2w);
    conv1_kernel<<<dim3(8, 8, BATCH), 256>>>(x, c1w, c1b);
    conv2_kernel<<<dim3(4, 8, BATCH), 256, C2_SMEM_B>>>(c2b);
    dense1_kernel<<<D1_SPLITS, 256>>>(d1w);
    dense1red_kernel<<<dim3(8, BATCH), 128>>>();
    dense23_kernel<<<BATCH, 128>>>(d1b, d2w, d2b, d3w, d3b);
    sampler_kernel<<<dim3(HW, BATCH), 256>>>(x, outw, outb, out);
}

// round 16
// speedup vs baseline: 1.5640x; 1.2284x over previous
#include <cuda_runtime.h>
#include <cuda_fp16.h>
#include <math.h>

// ---------------------------------------------------------------------------
// SpatialTransformerInputHead  (B=128, H=W=256, C=1)
//   conv1 5x5 1->14 + relu + maxpool2  (fp32 f32x2)         -> g_buf1 fp16 NHWC16
//   conv2 5x5 14->32 + relu + maxpool2 (fp16 HMMA, fp32 acc)-> g_buf2 fp16 NHWC
//   dense1 119072->120 (fp16 HMMA split-K, double-buffered)
//   dense 120->84 relu, 84->6 -> theta
//   bilinear grid sample + 1x1 conv + sigmoid -> [128,256,256,1]
// ---------------------------------------------------------------------------

typedef unsigned long long ull;
typedef unsigned int uint32;

#define BATCH 128
#define HW    256
#define P1    126
#define P2    61
#define FLAT  (61*61*32)   // 119072

#define D1_SPLITS 266      // ceil(119072/448)
#define D1_KCHUNK 448      // 7 tiles x 64 k
#define D1_TILES  7

// --------- scratch -----------------------------------------------------------
__device__ __half g_buf1[(size_t)BATCH*P1*P1*16];  // conv1 pooled, NHWC16, fp16
__device__ __half g_w16[25*32*24];                 // conv2 weights fp16 [tap][co][k24]
__device__ __half g_buf2[(size_t)BATCH*FLAT];      // conv2 pooled, NHWC flat, fp16
__device__ float  g_part[(size_t)D1_SPLITS*BATCH*128];  // padded n-stride 128
__device__ float  g_red[8*BATCH*120];
__device__ float  g_theta[BATCH*6];

// --------- helpers -----------------------------------------------------------
__device__ __forceinline__ ull pk2(float v) {
    ull r;
    asm("mov.b64 %0, {%1, %2};" : "=l"(r) : "f"(v), "f"(v));
    return r;
}
__device__ __forceinline__ void upk2(ull v, float& lo, float& hi) {
    asm("mov.b64 {%0, %1}, %2;" : "=f"(lo), "=f"(hi) : "l"(v));
}
#define FMA2(d, a, b) asm("fma.rn.f32x2 %0, %1, %2, %0;" : "+l"(d) : "l"(a), "l"(b))

__device__ __forceinline__ uint32 smem_u32(const void* p) {
    uint32 a;
    asm("{ .reg .u64 t; cvta.to.shared.u64 t, %1; cvt.u32.u64 %0, t; }"
        : "=r"(a) : "l"(p));
    return a;
}

#define MMA_F16(c, a0, a1, a2, a3, b0, b1)                                     \
    asm volatile(                                                              \
        "mma.sync.aligned.m16n8k16.row.col.f32.f16.f16.f32 "                   \
        "{%0,%1,%2,%3}, {%4,%5,%6,%7}, {%8,%9}, {%0,%1,%2,%3};"                \
        : "+f"((c)[0]), "+f"((c)[1]), "+f"((c)[2]), "+f"((c)[3])               \
        : "r"(a0), "r"(a1), "r"(a2), "r"(a3), "r"(b0), "r"(b1))

#define LDSM_X4(r0, r1, r2, r3, addr)                                          \
    asm volatile("ldmatrix.sync.aligned.m8n8.x4.shared.b16 {%0,%1,%2,%3}, [%4];" \
        : "=r"(r0), "=r"(r1), "=r"(r2), "=r"(r3) : "r"(addr))

// ===========================================================================
// wprep: conv2 weights HWIO fp32 -> fp16 [tap][co(32)][ci pad 24], once.
// ===========================================================================
__global__ void __launch_bounds__(256) wprep_kernel(const float* __restrict__ w)
{
    const int tap = blockIdx.x;
    for (int i = threadIdx.x; i < 768; i += 256) {
        int n = i / 24, k = i - n*24;
        float v = (k < 14) ? w[tap*448 + k*32 + n] : 0.f;
        g_w16[tap*768 + i] = __float2half_rn(v);
    }
}

// ===========================================================================
// conv1 (5x5, 1->14) + relu + maxpool2, fp32 f32x2 math, fp16 NHWC16 output.
// grid (8,8,128), 256 threads.
// ===========================================================================
__global__ void __launch_bounds__(256) conv1_kernel(
    const float* __restrict__ x, const float* __restrict__ w,
    const float* __restrict__ bias)
{
    __shared__ __align__(16) float sw[352];
    __shared__ __align__(16) float sb[16];
    __shared__ __align__(16) float sin_[36*36];

    const int b  = blockIdx.z;
    const int ox = blockIdx.x * 32;
    const int oy = blockIdx.y * 32;
    const int tid = threadIdx.x;

    for (int i = tid; i < 350; i += 256) sw[i] = w[i];
    if (tid < 14)  sb[tid] = bias[tid];

    const float* xb = x + (size_t)b * (HW*HW);
    for (int i = tid; i < 36*36; i += 256) {
        int r = i / 36, c = i % 36;
        int gy = oy + r, gx = ox + c;
        sin_[i] = (gy < HW && gx < HW) ? xb[gy*HW + gx] : 0.f;
    }
    __syncthreads();

    const int tx = tid & 15, ty = tid >> 4;

    ull acc[4][7];
#pragma unroll
    for (int p = 0; p < 4; ++p)
#pragma unroll
        for (int j = 0; j < 7; ++j) acc[p][j] = 0ull;

    const float* ib = sin_ + (2*ty)*36 + 2*tx;
#pragma unroll
    for (int dy = 0; dy < 5; ++dy) {
        const float* ra = ib + dy*36;
        const float* rb = ra + 36;
#pragma unroll
        for (int dx = 0; dx < 5; ++dx) {
            ull p00 = pk2(ra[dx]);
            ull p01 = pk2(ra[dx+1]);
            ull p10 = pk2(rb[dx]);
            ull p11 = pk2(rb[dx+1]);
            const ull* wp = (const ull*)&sw[(dy*5 + dx)*14];
#pragma unroll
            for (int j = 0; j < 7; ++j) {
                ull wv = wp[j];
                FMA2(acc[0][j], p00, wv);
                FMA2(acc[1][j], p01, wv);
                FMA2(acc[2][j], p10, wv);
                FMA2(acc[3][j], p11, wv);
            }
        }
    }

    const int x0 = blockIdx.x*16 + tx;
    const int y0 = blockIdx.y*16 + ty;
    if (x0 < P1 && y0 < P1) {
        union { uint4 u[2]; __half2 h2[8]; } pk;
#pragma unroll
        for (int j = 0; j < 7; ++j) {
            float l0,h0,l1,h1,l2,h2,l3,h3;
            upk2(acc[0][j], l0, h0);
            upk2(acc[1][j], l1, h1);
            upk2(acc[2][j], l2, h2);
            upk2(acc[3][j], l3, h3);
            float m0 = fmaxf(fmaxf(l0,l1), fmaxf(l2,l3)) + sb[2*j];
            float m1 = fmaxf(fmaxf(h0,h1), fmaxf(h2,h3)) + sb[2*j+1];
            pk.h2[j] = __float22half2_rn(make_float2(fmaxf(m0, 0.f), fmaxf(m1, 0.f)));
        }
        pk.h2[7] = __float22half2_rn(make_float2(0.f, 0.f));
        uint4* dst = (uint4*)(g_buf1 + ((size_t)(b*P1 + y0)*P1 + x0)*16);
        dst[0] = pk.u[0];
        dst[1] = pk.u[1];
    }
}

// ===========================================================================
// conv2 via fp16 mma.sync m16n8k16 (fp32 accum): 5x5 conv = 25 shifted GEMMs.
// Block: 8x16 pooled, 256 threads (8 warps), 2 blocks/SM.
// Epilogue: 2x2 maxpool + bias + relu -> fp16 NHWC flat g_buf2.
// ===========================================================================
#define C2_A_B    (720*48)                  // 34560 B (20 rows x 36 cols)
#define C2_W_B    (25*32*48)                // 38400 B
#define C2_SMEM_B (C2_A_B + C2_W_B + 128)   // 73088 B

__global__ void __launch_bounds__(256, 2) conv2_kernel(const float* __restrict__ bias)
{
    extern __shared__ __align__(16) unsigned char smem[];
    __half* At = (__half*)smem;                        // [pos 20x36][24]
    __half* Wt = (__half*)(smem + C2_A_B);             // [tap][co32][24]
    float*  sb = (float*)(smem + C2_A_B + C2_W_B);     // [32]

    const int b   = blockIdx.z;
    const int px0 = blockIdx.x * 16;
    const int py0 = blockIdx.y * 8;
    const int ix0 = px0 * 2;
    const int iy0 = py0 * 2;
    const int tid = threadIdx.x;

    // W: straight 38.4KB vector copy from preconverted fp16
    {
        const uint4* ws = (const uint4*)g_w16;
        uint4* wd = (uint4*)Wt;
        for (int i = tid; i < C2_W_B/16; i += 256) wd[i] = ws[i];
    }
    if (tid < 32) sb[tid] = bias[tid];

    // A tile: 20x36 positions, 32B fp16 copy + 16B zero pad (48B rows)
    for (int p = tid; p < 720; p += 256) {
        int r = p / 36, c = p - r*36;
        int gy = iy0 + r, gx = ix0 + c;
        uint4 u0 = make_uint4(0,0,0,0), u1 = u0;
        if (gy < P1 && gx < P1) {
            const uint4* s4 = (const uint4*)(g_buf1 + ((size_t)(b*P1 + gy)*P1 + gx)*16);
            u0 = s4[0]; u1 = s4[1];
        }
        uint4* d = (uint4*)(At + p*24);
        d[0] = u0; d[1] = u1; d[2] = make_uint4(0,0,0,0);
    }
    __syncthreads();

    const int warp = tid >> 5, lane = tid & 31;
    const int y0 = 2 * warp;
    const uint32 atb = smem_u32(At);
    const uint32 wtb = smem_u32(Wt);

    const uint32 aoff = (uint32)((lane & 15)*48 + (lane >> 4)*16);
    const uint32 boff = (uint32)(((lane & 7) + ((lane >> 4) & 1)*8)*48
                                 + ((lane >> 3) & 1)*16);

    float cacc[2][2][4][4];
#pragma unroll
    for (int s = 0; s < 2; ++s)
#pragma unroll
        for (int xh = 0; xh < 2; ++xh)
#pragma unroll
            for (int nf = 0; nf < 4; ++nf)
#pragma unroll
                for (int k = 0; k < 4; ++k) cacc[s][xh][nf][k] = 0.f;

#pragma unroll 1
    for (int tap = 0; tap < 25; ++tap) {
        const int dy = tap / 5, dx = tap - 5*dy;

        const uint32 wb = wtb + (uint32)(tap*1536) + boff;
        uint32 b00, b01, b10, b11, b20, b21, b30, b31;
        LDSM_X4(b00, b01, b10, b11, wb);
        LDSM_X4(b20, b21, b30, b31, wb + 768);

#pragma unroll
        for (int s = 0; s < 2; ++s) {
            const int rowbase = (y0 + s + dy)*36 + dx;
#pragma unroll
            for (int xh = 0; xh < 2; ++xh) {
                uint32 a0, a1, a2, a3;
                LDSM_X4(a0, a1, a2, a3,
                        atb + (uint32)((rowbase + xh*16)*48) + aoff);
                MMA_F16(cacc[s][xh][0], a0, a1, a2, a3, b00, b01);
                MMA_F16(cacc[s][xh][1], a0, a1, a2, a3, b10, b11);
                MMA_F16(cacc[s][xh][2], a0, a1, a2, a3, b20, b21);
                MMA_F16(cacc[s][xh][3], a0, a1, a2, a3, b30, b31);
            }
        }
    }

    // epilogue: 2x2 maxpool + bias + relu -> fp16 NHWC
    const int py = py0 + warp;
    const int r  = lane >> 2;
    const bool active = ((r & 1) == 0);
    const int j = r >> 1;
    const int n0 = (lane & 3) * 2;

#pragma unroll
    for (int xh = 0; xh < 2; ++xh)
#pragma unroll
    for (int nf = 0; nf < 4; ++nf) {
        float m0 = fmaxf(cacc[0][xh][nf][0], cacc[1][xh][nf][0]);
        float m1 = fmaxf(cacc[0][xh][nf][1], cacc[1][xh][nf][1]);
        float m2 = fmaxf(cacc[0][xh][nf][2], cacc[1][xh][nf][2]);
        float m3 = fmaxf(cacc[0][xh][nf][3], cacc[1][xh][nf][3]);
        float o0 = fmaxf(m0, __shfl_down_sync(0xffffffffu, m0, 4));
        float o1 = fmaxf(m1, __shfl_down_sync(0xffffffffu, m1, 4));
        float o2 = fmaxf(m2, __shfl_down_sync(0xffffffffu, m2, 4));
        float o3 = fmaxf(m3, __shfl_down_sync(0xffffffffu, m3, 4));
        if (active && py < P2) {
            const int ch  = nf*8 + n0;
            const float b0v = sb[ch], b1v = sb[ch+1];
            const int pxa = px0 + xh*8 + j;
            const int pxb = pxa + 4;
            if (pxa < P2) {
                __half2 v = __float22half2_rn(
                    make_float2(fmaxf(o0 + b0v, 0.f), fmaxf(o1 + b1v, 0.f)));
                *(__half2*)(g_buf2 + (((size_t)b*P2 + py)*P2 + pxa)*32 + ch) = v;
            }
            if (pxb < P2) {
                __half2 v = __float22half2_rn(
                    make_float2(fmaxf(o2 + b0v, 0.f), fmaxf(o3 + b1v, 0.f)));
                *(__half2*)(g_buf2 + (((size_t)b*P2 + py)*P2 + pxb)*32 + ch) = v;
            }
        }
    }
}

// ===========================================================================
// dense1 via fp16 HMMA split-K v2: [128 x K] @ [K x 120] -> fp32 partials.
// grid 266 blocks (K-chunk 448 = 7 double-buffered 64-k tiles), 256 threads.
// 8 warps = 4 M-groups (32 rows) x 2 N-groups (64 cols); per warp per k16:
// 2 A-ldsm.x4 + 4 B-ldsm.x4 + 16 MMA.  Rows padded to 72 halfs (144B stride:
// LDSM row-starts at word-banks 4r -> exact 32-bank cover, conflict-free).
// ===========================================================================
#define D1_TILE_H  (128*72)                   // halfs per tile buffer
#define D1_SMEM_B  (4 * D1_TILE_H * 2)        // A[2] + W[2] = 73728 B

__global__ void __launch_bounds__(256, 2) dense1_kernel(const float* __restrict__ w)
{
    extern __shared__ __align__(16) __half dsm[];
    __half* Asm = dsm;                  // [2][128 m][72]
    __half* Wsm = dsm + 2*D1_TILE_H;    // [2][128 n][72]

    const int k0   = blockIdx.x * D1_KCHUNK;
    const int kend = min(k0 + D1_KCHUNK, FLAT);
    const int tid  = threadIdx.x;
    const int wid  = tid >> 5, lane = tid & 31;
    const int m0   = (wid >> 1) * 32;
    const int n0   = (wid & 1) * 64;

    const uint32 aoff = (uint32)(m0*144 + (lane & 15)*144 + (lane >> 4)*16);
    const uint32 boff = (uint32)(n0*144 + ((lane & 7) + ((lane >> 4) & 1)*8)*144
                                 + ((lane >> 3) & 1)*16);

    float acc[2][8][4];
#pragma unroll
    for (int mt = 0; mt < 2; ++mt)
#pragma unroll
        for (int nf = 0; nf < 8; ++nf)
#pragma unroll
            for (int k = 0; k < 4; ++k) acc[mt][nf][k] = 0.f;

    // ---- tile fill ----
    auto fill = [&](int t, int buf) {
        const int kt = k0 + t*64;
        __half* Ab = Asm + buf*D1_TILE_H;
        __half* Wb = Wsm + buf*D1_TILE_H;
#pragma unroll
        for (int i = tid; i < 1024; i += 256) {        // A: 128 rows x 8 vec8
            int r = i & 127, q = i >> 7;
            int k = kt + q*8;
            uint4 v = make_uint4(0,0,0,0);
            if (k < kend) v = *(const uint4*)(g_buf2 + (size_t)r*FLAT + k);
            *(uint4*)(Ab + r*72 + q*8) = v;
        }
#pragma unroll
        for (int i = tid; i < 4096; i += 256) {        // W: 32 kk-pairs x 128 n
            int kkp = i >> 7, n = i & 127;
            int k = kt + 2*kkp;
            float v0 = (n < 120 && k     < kend) ? w[(size_t)k*120 + n] : 0.f;
            float v1 = (n < 120 && k + 1 < kend) ? w[(size_t)(k+1)*120 + n] : 0.f;
            *(__half2*)(Wb + n*72 + 2*kkp) = __float22half2_rn(make_float2(v0, v1));
        }
    };

    fill(0, 0);
    __syncthreads();

#pragma unroll 1
    for (int t = 0; t < D1_TILES; ++t) {
        const int buf = t & 1;
        if (t + 1 < D1_TILES) fill(t + 1, buf ^ 1);

        const uint32 ab = smem_u32(Asm + buf*D1_TILE_H);
        const uint32 wb = smem_u32(Wsm + buf*D1_TILE_H);

#pragma unroll
        for (int ks = 0; ks < 4; ++ks) {
            const uint32 koff = (uint32)(ks*32);
            uint32 bfr[4][4];
#pragma unroll
            for (int np = 0; np < 4; ++np)
                LDSM_X4(bfr[np][0], bfr[np][1], bfr[np][2], bfr[np][3],
                        wb + boff + (uint32)(np*16*144) + koff);
#pragma unroll
            for (int mt = 0; mt < 2; ++mt) {
                uint32 a0, a1, a2, a3;
                LDSM_X4(a0, a1, a2, a3, ab + aoff + (uint32)(mt*16*144) + koff);
#pragma unroll
                for (int np = 0; np < 4; ++np) {
                    MMA_F16(acc[mt][2*np],   a0, a1, a2, a3, bfr[np][0], bfr[np][1]);
                    MMA_F16(acc[mt][2*np+1], a0, a1, a2, a3, bfr[np][2], bfr[np][3]);
                }
            }
        }
        __syncthreads();
    }

    // store fp32 partials: g_part[(split*128 + m)*128 + n]
    const int gr = lane >> 2;
    const int c2 = (lane & 3) * 2;
    float* p = g_part + ((size_t)blockIdx.x*BATCH + m0)*128 + n0;
#pragma unroll
    for (int mt = 0; mt < 2; ++mt)
#pragma unroll
        for (int nf = 0; nf < 8; ++nf) {
            int n = nf*8 + c2;
            float* pr = p + (size_t)(mt*16 + gr)*128 + n;
            *(float2*)(pr)        = make_float2(acc[mt][nf][0], acc[mt][nf][1]);
            *(float2*)(pr + 8*128) = make_float2(acc[mt][nf][2], acc[mt][nf][3]);
        }
}

// ===========================================================================
// dense1red: stage-1 reduction of 266 splits in 7 chunks of 38.
// grid (7, 128), 128 threads.
// ===========================================================================
__global__ void __launch_bounds__(128) dense1red_kernel()
{
    const int c = blockIdx.x;          // chunk 0..6
    const int b = blockIdx.y;
    const int t = threadIdx.x;
    if (t >= 120) return;

    const size_t stride = (size_t)BATCH * 128;
    const float* gp = g_part + ((size_t)(c*38)*BATCH + b)*128 + t;

    float s0 = 0.f, s1 = 0.f, s2 = 0.f, s3 = 0.f;
#pragma unroll 2
    for (int i = 0; i < 36; i += 4) {
        s0 += gp[(size_t)(i+0)*stride];
        s1 += gp[(size_t)(i+1)*stride];
        s2 += gp[(size_t)(i+2)*stride];
        s3 += gp[(size_t)(i+3)*stride];
    }
    s0 += gp[(size_t)36*stride];
    s1 += gp[(size_t)37*stride];
    g_red[((size_t)c*BATCH + b)*120 + t] = (s0 + s1) + (s2 + s3);
}

// ===========================================================================
// dense23: reduce 7 stage-1 partials + bias + relu -> h1;
//          h2 = relu(h1 @ d2_w + b2);  theta = h2 @ d3_w + b3.
// ===========================================================================
__global__ void __launch_bounds__(128) dense23_kernel(
    const float* __restrict__ d1b,
    const float* __restrict__ d2w, const float* __restrict__ d2b,
    const float* __restrict__ d3w, const float* __restrict__ d3b)
{
    __shared__ float h1[120];
    __shared__ float h2[84];
    const int b = blockIdx.x, t = threadIdx.x;

    if (t < 120) {
        const float* gp = g_red + (size_t)b*120 + t;
        float s = d1b[t];
#pragma unroll
        for (int i = 0; i < 7; ++i)
            s += gp[(size_t)i*BATCH*120];
        h1[t] = fmaxf(s, 0.f);
    }
    __syncthreads();
    if (t < 84) {
        float s = d2b[t];
#pragma unroll 4
        for (int k = 0; k < 120; ++k)
            s = fmaf(h1[k], d2w[k*84 + t], s);
        h2[t] = fmaxf(s, 0.f);
    }
    __syncthreads();
    if (t < 6) {
        float s = d3b[t];
#pragma unroll 4
        for (int k = 0; k < 84; ++k)
            s = fmaf(h2[k], d3w[k*6 + t], s);
        g_theta[b*6 + t] = s;
    }
}

// ===========================================================================
// sampler: affine grid + bilinear sample + 1x1 conv + sigmoid.
// ===========================================================================
__global__ void __launch_bounds__(256) sampler_kernel(
    const float* __restrict__ x, const float* __restrict__ ow,
    const float* __restrict__ ob, float* __restrict__ out)
{
    __shared__ float th[6];
    const int b = blockIdx.y;
    const int h = blockIdx.x;
    const int w = threadIdx.x;
    if (w < 6) th[w] = g_theta[b*6 + w];
    __syncthreads();

    const float gx = (float)w * (2.f/256.f) - 1.f;
    const float gy = (float)h * (2.f/256.f) - 1.f;
    const float px = (th[0]*gx + th[1]*gy + th[2] + 1.f) * 128.f;
    const float py = (th[3]*gx + th[4]*gy + th[5] + 1.f) * 128.f;

    const int fx = (int)floorf(px);
    const int fy = (int)floorf(py);
    const int x1 = min(max(fx,     0), HW-1);
    const int x2 = min(max(fx + 1, 0), HW-1);
    const int y1 = min(max(fy,     0), HW-1);
    const int y2 = min(max(fy + 1, 0), HW-1);

    const float* img = x + (size_t)b * (HW*HW);
    const float p11 = img[y1*HW + x1];
    const float p12 = img[y2*HW + x1];
    const float p21 = img[y1*HW + x2];
    const float p22 = img[y2*HW + x2];

    const float wx1 = (float)x2 - px;
    const float wx2 = px - (float)x1;
    const float wy1 = (float)y2 - py;
    const float wy2 = py - (float)y1;

    const float r = wx1*(wy1*p11 + wy2*p12) + wx2*(wy1*p21 + wy2*p22);
    const float t = r * __ldg(ow) + __ldg(ob);
    out[((size_t)b*HW + h)*HW + w] = 1.f / (1.f + expf(-t));
}

// ===========================================================================
// launch
// ===========================================================================
extern "C" void kernel_launch(void* const* d_in, const int* in_sizes, int n_in,
                              void* d_out, int out_size)
{
    const float* x      = (const float*)d_in[0];
    const float* c1w    = (const float*)d_in[1];
    const float* c1b    = (const float*)d_in[2];
    const float* c2w    = (const float*)d_in[3];
    const float* c2b    = (const float*)d_in[4];
    const float* d1w    = (const float*)d_in[5];
    const float* d1b    = (const float*)d_in[6];
    const float* d2w    = (const float*)d_in[7];
    const float* d2b    = (const float*)d_in[8];
    const float* d3w    = (const float*)d_in[9];
    const float* d3b    = (const float*)d_in[10];
    const float* outw   = (const float*)d_in[11];
    const float* outb   = (const float*)d_in[12];
    float* out = (float*)d_out;

    (void)in_sizes; (void)n_in; (void)out_size;

    cudaFuncSetAttribute(conv2_kernel,
                         cudaFuncAttributeMaxDynamicSharedMemorySize, C2_SMEM_B);
    cudaFuncSetAttribute(dense1_kernel,
                         cudaFuncAttributeMaxDynamicSharedMemorySize, D1_SMEM_B);

    wprep_kernel<<<25, 256>>>(c2w);
    conv1_kernel<<<dim3(8, 8, BATCH), 256>>>(x, c1w, c1b);
    conv2_kernel<<<dim3(4, 8, BATCH), 256, C2_SMEM_B>>>(c2b);
    dense1_kernel<<<D1_SPLITS, 256, D1_SMEM_B>>>(d1w);
    dense1red_kernel<<<dim3(7, BATCH), 128>>>();
    dense23_kernel<<<BATCH, 128>>>(d1b, d2w, d2b, d3w, d3b);
    sampler_kernel<<<dim3(HW, BATCH), 256>>>(x, outw, outb, out);
}

// round 17
// speedup vs baseline: 1.8030x; 1.1528x over previous
#include <cuda_runtime.h>
#include <cuda_fp16.h>
#include <math.h>

// ---------------------------------------------------------------------------
// SpatialTransformerInputHead  (B=128, H=W=256, C=1)
//   conv1 5x5 1->14 + relu + maxpool2  (fp16 HMMA, fp32 acc)-> g_buf1 fp16 NHWC16
//   conv2 5x5 14->32 + relu + maxpool2 (fp16 HMMA, fp32 acc)-> g_buf2 fp16 NHWC
//   dense1 119072->120 (fp16 HMMA split-K, double-buffered)
//   dense 120->84 relu, 84->6 -> theta
//   bilinear grid sample + 1x1 conv + sigmoid -> [128,256,256,1]
// ---------------------------------------------------------------------------

typedef unsigned long long ull;
typedef unsigned int uint32;

#define BATCH 128
#define HW    256
#define P1    126
#define P2    61
#define FLAT  (61*61*32)   // 119072

#define D1_SPLITS 266      // ceil(119072/448)
#define D1_KCHUNK 448      // 7 tiles x 64 k
#define D1_TILES  7

// --------- scratch -----------------------------------------------------------
__device__ __half g_buf1[(size_t)BATCH*P1*P1*16];  // conv1 pooled, NHWC16, fp16
__device__ __half g_w16[25*32*24];                 // conv2 weights fp16 [tap][co][k24]
__device__ __half g_w1[16*32];                     // conv1 weights fp16 [n16][k32]
__device__ __half g_buf2[(size_t)BATCH*FLAT];      // conv2 pooled, NHWC flat, fp16
__device__ float  g_part[(size_t)D1_SPLITS*BATCH*128];  // padded n-stride 128
__device__ float  g_red[8*BATCH*120];
__device__ float  g_theta[BATCH*6];

// --------- helpers -----------------------------------------------------------
__device__ __forceinline__ ull pk2(float v) {
    ull r;
    asm("mov.b64 %0, {%1, %2};" : "=l"(r) : "f"(v), "f"(v));
    return r;
}
#define FMA2(d, a, b) asm("fma.rn.f32x2 %0, %1, %2, %0;" : "+l"(d) : "l"(a), "l"(b))

__device__ __forceinline__ uint32 smem_u32(const void* p) {
    uint32 a;
    asm("{ .reg .u64 t; cvta.to.shared.u64 t, %1; cvt.u32.u64 %0, t; }"
        : "=r"(a) : "l"(p));
    return a;
}
__device__ __forceinline__ uint32 packh2(__half lo, __half hi) {
    __half2 h = __halves2half2(lo, hi);
    return *(uint32*)&h;
}

#define MMA_F16(c, a0, a1, a2, a3, b0, b1)                                     \
    asm volatile(                                                              \
        "mma.sync.aligned.m16n8k16.row.col.f32.f16.f16.f32 "                   \
        "{%0,%1,%2,%3}, {%4,%5,%6,%7}, {%8,%9}, {%0,%1,%2,%3};"                \
        : "+f"((c)[0]), "+f"((c)[1]), "+f"((c)[2]), "+f"((c)[3])               \
        : "r"(a0), "r"(a1), "r"(a2), "r"(a3), "r"(b0), "r"(b1))

#define LDSM_X4(r0, r1, r2, r3, addr)                                          \
    asm volatile("ldmatrix.sync.aligned.m8n8.x4.shared.b16 {%0,%1,%2,%3}, [%4];" \
        : "=r"(r0), "=r"(r1), "=r"(r2), "=r"(r3) : "r"(addr))

// ===========================================================================
// wprep: conv2 weights HWIO fp32 -> fp16 [tap][co(32)][ci pad 24], once.
// ===========================================================================
__global__ void __launch_bounds__(256) wprep_kernel(const float* __restrict__ w)
{
    const int tap = blockIdx.x;
    for (int i = threadIdx.x; i < 768; i += 256) {
        int n = i / 24, k = i - n*24;
        float v = (k < 14) ? w[tap*448 + k*32 + n] : 0.f;
        g_w16[tap*768 + i] = __float2half_rn(v);
    }
}

// wprep1: conv1 weights [25 tap][14 co] fp32 -> fp16 g_w1[n16][k32]
__global__ void __launch_bounds__(512) wprep1_kernel(const float* __restrict__ w)
{
    const int i = threadIdx.x;
    if (i < 512) {
        int n = i >> 5, k = i & 31;
        float v = (k < 25 && n < 14) ? w[k*14 + n] : 0.f;
        g_w1[i] = __float2half_rn(v);
    }
}

// ===========================================================================
// conv1 via fp16 mma.sync m16n8k16 (fp32 accum), register-built im2col frags.
// M = conv positions (16 y x 32 x per block), N = 14(pad16), K = 25(pad32).
// Block: 8x16 pooled, 256 threads (8 warps); warp w = pooled row py0+w.
// grid (8,16,128).  Epilogue identical to conv2's maxpool+bias+relu.
// ===========================================================================
__global__ void __launch_bounds__(256, 2) conv1_kernel(
    const float* __restrict__ x, const float* __restrict__ bias)
{
    __shared__ __half xt[20*36];        // input tile, fp16
    __shared__ float  sb[16];

    const int b   = blockIdx.z;
    const int px0 = blockIdx.x * 16;
    const int py0 = blockIdx.y * 8;
    const int ix0 = px0 * 2;
    const int iy0 = py0 * 2;
    const int tid = threadIdx.x;

    if (tid < 14) sb[tid] = bias[tid];
    if (tid >= 14 && tid < 16) sb[tid] = 0.f;

    const float* xb = x + (size_t)b * (HW*HW);
    for (int i = tid; i < 720; i += 256) {
        int r = i / 36, c = i - r*36;
        int gy = iy0 + r, gx = ix0 + c;
        xt[i] = (gy < HW && gx < HW) ? __float2half_rn(xb[gy*HW + gx])
                                     : __float2half_rn(0.f);
    }
    __syncthreads();

    const int warp = tid >> 5, lane = tid & 31;
    const int gr = lane >> 2;            // fragment row group (0..7)
    const int k2 = (lane & 3) * 2;       // fragment k pair base

    // B fragments from g_w1 (L1-resident after first block): bf[kc][nf][2]
    uint32 bf[2][2][2];
#pragma unroll
    for (int kc = 0; kc < 2; ++kc)
#pragma unroll
        for (int nf = 0; nf < 2; ++nf) {
            const __half* wr = g_w1 + (nf*8 + gr)*32 + kc*16 + k2;
            bf[kc][nf][0] = *(const uint32*)(wr);       // taps k2,k2+1
            bf[kc][nf][1] = *(const uint32*)(wr + 8);   // taps k2+8,k2+9
        }

    float cacc[2][2][2][4];
#pragma unroll
    for (int s = 0; s < 2; ++s)
#pragma unroll
        for (int xh = 0; xh < 2; ++xh)
#pragma unroll
            for (int nf = 0; nf < 2; ++nf)
#pragma unroll
                for (int k = 0; k < 4; ++k) cacc[s][xh][nf][k] = 0.f;

    const __half hz = __float2half_rn(0.f);

#pragma unroll
    for (int kc = 0; kc < 2; ++kc) {
        // the 4 tap indices this lane needs for its a-frag in this k-chunk
        const int t0 = kc*16 + k2, t1 = t0 + 1, t2 = t0 + 8, t3 = t0 + 9;
        const bool v0 = (t0 < 25), v1 = (t1 < 25), v2 = (t2 < 25), v3 = (t3 < 25);
        const int o0 = v0 ? (t0/5)*36 + (t0 % 5) : 0;
        const int o1 = v1 ? (t1/5)*36 + (t1 % 5) : 0;
        const int o2 = v2 ? (t2/5)*36 + (t2 % 5) : 0;
        const int o3 = v3 ? (t3/5)*36 + (t3 % 5) : 0;

#pragma unroll
        for (int s = 0; s < 2; ++s) {
            const int ybase = (2*warp + s)*36;
#pragma unroll
            for (int xh = 0; xh < 2; ++xh) {
                const int xA = ybase + xh*16 + gr;     // row gr
                const int xB = xA + 8;                 // row gr+8
                uint32 a0 = packh2(v0 ? xt[xA + o0] : hz, v1 ? xt[xA + o1] : hz);
                uint32 a1 = packh2(v0 ? xt[xB + o0] : hz, v1 ? xt[xB + o1] : hz);
                uint32 a2 = packh2(v2 ? xt[xA + o2] : hz, v3 ? xt[xA + o3] : hz);
                uint32 a3 = packh2(v2 ? xt[xB + o2] : hz, v3 ? xt[xB + o3] : hz);
                MMA_F16(cacc[s][xh][0], a0, a1, a2, a3, bf[kc][0][0], bf[kc][0][1]);
                MMA_F16(cacc[s][xh][1], a0, a1, a2, a3, bf[kc][1][0], bf[kc][1][1]);
            }
        }
    }

    // epilogue: 2x2 maxpool (y across s, x across frag-row pairs) + bias + relu
    const int py = py0 + warp;
    const int r  = lane >> 2;
    const bool active = ((r & 1) == 0);
    const int j = r >> 1;
    const int n0 = (lane & 3) * 2;

#pragma unroll
    for (int xh = 0; xh < 2; ++xh)
#pragma unroll
    for (int nf = 0; nf < 2; ++nf) {
        float m0 = fmaxf(cacc[0][xh][nf][0], cacc[1][xh][nf][0]);
        float m1 = fmaxf(cacc[0][xh][nf][1], cacc[1][xh][nf][1]);
        float m2 = fmaxf(cacc[0][xh][nf][2], cacc[1][xh][nf][2]);
        float m3 = fmaxf(cacc[0][xh][nf][3], cacc[1][xh][nf][3]);
        float o0 = fmaxf(m0, __shfl_down_sync(0xffffffffu, m0, 4));
        float o1 = fmaxf(m1, __shfl_down_sync(0xffffffffu, m1, 4));
        float o2 = fmaxf(m2, __shfl_down_sync(0xffffffffu, m2, 4));
        float o3 = fmaxf(m3, __shfl_down_sync(0xffffffffu, m3, 4));
        if (active && py < P1) {
            const int ch  = nf*8 + n0;
            const bool pad = (ch >= 14);
            const float b0v = sb[ch], b1v = sb[ch < 15 ? ch+1 : 15];
            const int pxa = px0 + xh*8 + j;
            const int pxb = pxa + 4;
            if (pxa < P1) {
                __half2 v = pad ? __float22half2_rn(make_float2(0.f, 0.f))
                    : __float22half2_rn(make_float2(fmaxf(o0 + b0v, 0.f),
                                                    fmaxf(o1 + b1v, 0.f)));
                *(__half2*)(g_buf1 + ((size_t)(b*P1 + py)*P1 + pxa)*16 + ch) = v;
            }
            if (pxb < P1) {
                __half2 v = pad ? __float22half2_rn(make_float2(0.f, 0.f))
                    : __float22half2_rn(make_float2(fmaxf(o2 + b0v, 0.f),
                                                    fmaxf(o3 + b1v, 0.f)));
                *(__half2*)(g_buf1 + ((size_t)(b*P1 + py)*P1 + pxb)*16 + ch) = v;
            }
        }
    }
}

// ===========================================================================
// conv2 via fp16 mma.sync m16n8k16 (fp32 accum): 5x5 conv = 25 shifted GEMMs.
// Block: 8x16 pooled, 256 threads (8 warps), 2 blocks/SM.
// Epilogue: 2x2 maxpool + bias + relu -> fp16 NHWC flat g_buf2.
// ===========================================================================
#define C2_A_B    (720*48)                  // 34560 B (20 rows x 36 cols)
#define C2_W_B    (25*32*48)                // 38400 B
#define C2_SMEM_B (C2_A_B + C2_W_B + 128)   // 73088 B

__global__ void __launch_bounds__(256, 2) conv2_kernel(const float* __restrict__ bias)
{
    extern __shared__ __align__(16) unsigned char smem[];
    __half* At = (__half*)smem;                        // [pos 20x36][24]
    __half* Wt = (__half*)(smem + C2_A_B);             // [tap][co32][24]
    float*  sb = (float*)(smem + C2_A_B + C2_W_B);     // [32]

    const int b   = blockIdx.z;
    const int px0 = blockIdx.x * 16;
    const int py0 = blockIdx.y * 8;
    const int ix0 = px0 * 2;
    const int iy0 = py0 * 2;
    const int tid = threadIdx.x;

    // W: straight 38.4KB vector copy from preconverted fp16
    {
        const uint4* ws = (const uint4*)g_w16;
        uint4* wd = (uint4*)Wt;
        for (int i = tid; i < C2_W_B/16; i += 256) wd[i] = ws[i];
    }
    if (tid < 32) sb[tid] = bias[tid];

    // A tile: 20x36 positions, 32B fp16 copy + 16B zero pad (48B rows)
    for (int p = tid; p < 720; p += 256) {
        int r = p / 36, c = p - r*36;
        int gy = iy0 + r, gx = ix0 + c;
        uint4 u0 = make_uint4(0,0,0,0), u1 = u0;
        if (gy < P1 && gx < P1) {
            const uint4* s4 = (const uint4*)(g_buf1 + ((size_t)(b*P1 + gy)*P1 + gx)*16);
            u0 = s4[0]; u1 = s4[1];
        }
        uint4* d = (uint4*)(At + p*24);
        d[0] = u0; d[1] = u1; d[2] = make_uint4(0,0,0,0);
    }
    __syncthreads();

    const int warp = tid >> 5, lane = tid & 31;
    const int y0 = 2 * warp;
    const uint32 atb = smem_u32(At);
    const uint32 wtb = smem_u32(Wt);

    const uint32 aoff = (uint32)((lane & 15)*48 + (lane >> 4)*16);
    const uint32 boff = (uint32)(((lane & 7) + ((lane >> 4) & 1)*8)*48
                                 + ((lane >> 3) & 1)*16);

    float cacc[2][2][4][4];
#pragma unroll
    for (int s = 0; s < 2; ++s)
#pragma unroll
        for (int xh = 0; xh < 2; ++xh)
#pragma unroll
            for (int nf = 0; nf < 4; ++nf)
#pragma unroll
                for (int k = 0; k < 4; ++k) cacc[s][xh][nf][k] = 0.f;

#pragma unroll 1
    for (int tap = 0; tap < 25; ++tap) {
        const int dy = tap / 5, dx = tap - 5*dy;

        const uint32 wb = wtb + (uint32)(tap*1536) + boff;
        uint32 b00, b01, b10, b11, b20, b21, b30, b31;
        LDSM_X4(b00, b01, b10, b11, wb);
        LDSM_X4(b20, b21, b30, b31, wb + 768);

#pragma unroll
        for (int s = 0; s < 2; ++s) {
            const int rowbase = (y0 + s + dy)*36 + dx;
#pragma unroll
            for (int xh = 0; xh < 2; ++xh) {
                uint32 a0, a1, a2, a3;
                LDSM_X4(a0, a1, a2, a3,
                        atb + (uint32)((rowbase + xh*16)*48) + aoff);
                MMA_F16(cacc[s][xh][0], a0, a1, a2, a3, b00, b01);
                MMA_F16(cacc[s][xh][1], a0, a1, a2, a3, b10, b11);
                MMA_F16(cacc[s][xh][2], a0, a1, a2, a3, b20, b21);
                MMA_F16(cacc[s][xh][3], a0, a1, a2, a3, b30, b31);
            }
        }
    }

    // epilogue: 2x2 maxpool + bias + relu -> fp16 NHWC
    const int py = py0 + warp;
    const int r  = lane >> 2;
    const bool active = ((r & 1) == 0);
    const int j = r >> 1;
    const int n0 = (lane & 3) * 2;

#pragma unroll
    for (int xh = 0; xh < 2; ++xh)
#pragma unroll
    for (int nf = 0; nf < 4; ++nf) {
        float m0 = fmaxf(cacc[0][xh][nf][0], cacc[1][xh][nf][0]);
        float m1 = fmaxf(cacc[0][xh][nf][1], cacc[1][xh][nf][1]);
        float m2 = fmaxf(cacc[0][xh][nf][2], cacc[1][xh][nf][2]);
        float m3 = fmaxf(cacc[0][xh][nf][3], cacc[1][xh][nf][3]);
        float o0 = fmaxf(m0, __shfl_down_sync(0xffffffffu, m0, 4));
        float o1 = fmaxf(m1, __shfl_down_sync(0xffffffffu, m1, 4));
        float o2 = fmaxf(m2, __shfl_down_sync(0xffffffffu, m2, 4));
        float o3 = fmaxf(m3, __shfl_down_sync(0xffffffffu, m3, 4));
        if (active && py < P2) {
            const int ch  = nf*8 + n0;
            const float b0v = sb[ch], b1v = sb[ch+1];
            const int pxa = px0 + xh*8 + j;
            const int pxb = pxa + 4;
            if (pxa < P2) {
                __half2 v = __float22half2_rn(
                    make_float2(fmaxf(o0 + b0v, 0.f), fmaxf(o1 + b1v, 0.f)));
                *(__half2*)(g_buf2 + (((size_t)b*P2 + py)*P2 + pxa)*32 + ch) = v;
            }
            if (pxb < P2) {
                __half2 v = __float22half2_rn(
                    make_float2(fmaxf(o2 + b0v, 0.f), fmaxf(o3 + b1v, 0.f)));
                *(__half2*)(g_buf2 + (((size_t)b*P2 + py)*P2 + pxb)*32 + ch) = v;
            }
        }
    }
}

// ===========================================================================
// dense1 via fp16 HMMA split-K v2: [128 x K] @ [K x 120] -> fp32 partials.
// grid 266 blocks (K-chunk 448 = 7 double-buffered 64-k tiles), 256 threads.
// 8 warps = 4 M-groups (32 rows) x 2 N-groups (64 cols).
// ===========================================================================
#define D1_TILE_H  (128*72)                   // halfs per tile buffer
#define D1_SMEM_B  (4 * D1_TILE_H * 2)        // A[2] + W[2] = 73728 B

__global__ void __launch_bounds__(256, 2) dense1_kernel(const float* __restrict__ w)
{
    extern __shared__ __align__(16) __half dsm[];
    __half* Asm = dsm;                  // [2][128 m][72]
    __half* Wsm = dsm + 2*D1_TILE_H;    // [2][128 n][72]

    const int k0   = blockIdx.x * D1_KCHUNK;
    const int kend = min(k0 + D1_KCHUNK, FLAT);
    const int tid  = threadIdx.x;
    const int wid  = tid >> 5, lane = tid & 31;
    const int m0   = (wid >> 1) * 32;
    const int n0   = (wid & 1) * 64;

    const uint32 aoff = (uint32)(m0*144 + (lane & 15)*144 + (lane >> 4)*16);
    const uint32 boff = (uint32)(n0*144 + ((lane & 7) + ((lane >> 4) & 1)*8)*144
                                 + ((lane >> 3) & 1)*16);

    float acc[2][8][4];
#pragma unroll
    for (int mt = 0; mt < 2; ++mt)
#pragma unroll
        for (int nf = 0; nf < 8; ++nf)
#pragma unroll
            for (int k = 0; k < 4; ++k) acc[mt][nf][k] = 0.f;

    auto fill = [&](int t, int buf) {
        const int kt = k0 + t*64;
        __half* Ab = Asm + buf*D1_TILE_H;
        __half* Wb = Wsm + buf*D1_TILE_H;
#pragma unroll
        for (int i = tid; i < 1024; i += 256) {        // A: 128 rows x 8 vec8
            int r = i & 127, q = i >> 7;
            int k = kt + q*8;
            uint4 v = make_uint4(0,0,0,0);
            if (k < kend) v = *(const uint4*)(g_buf2 + (size_t)r*FLAT + k);
            *(uint4*)(Ab + r*72 + q*8) = v;
        }
#pragma unroll
        for (int i = tid; i < 4096; i += 256) {        // W: 32 kk-pairs x 128 n
            int kkp = i >> 7, n = i & 127;
            int k = kt + 2*kkp;
            float v0 = (n < 120 && k     < kend) ? w[(size_t)k*120 + n] : 0.f;
            float v1 = (n < 120 && k + 1 < kend) ? w[(size_t)(k+1)*120 + n] : 0.f;
            *(__half2*)(Wb + n*72 + 2*kkp) = __float22half2_rn(make_float2(v0, v1));
        }
    };

    fill(0, 0);
    __syncthreads();

#pragma unroll 1
    for (int t = 0; t < D1_TILES; ++t) {
        const int buf = t & 1;
        if (t + 1 < D1_TILES) fill(t + 1, buf ^ 1);

        const uint32 ab = smem_u32(Asm + buf*D1_TILE_H);
        const uint32 wb = smem_u32(Wsm + buf*D1_TILE_H);

#pragma unroll
        for (int ks = 0; ks < 4; ++ks) {
            const uint32 koff = (uint32)(ks*32);
            uint32 bfr[4][4];
#pragma unroll
            for (int np = 0; np < 4; ++np)
                LDSM_X4(bfr[np][0], bfr[np][1], bfr[np][2], bfr[np][3],
                        wb + boff + (uint32)(np*16*144) + koff);
#pragma unroll
            for (int mt = 0; mt < 2; ++mt) {
                uint32 a0, a1, a2, a3;
                LDSM_X4(a0, a1, a2, a3, ab + aoff + (uint32)(mt*16*144) + koff);
#pragma unroll
                for (int np = 0; np < 4; ++np) {
                    MMA_F16(acc[mt][2*np],   a0, a1, a2, a3, bfr[np][0], bfr[np][1]);
                    MMA_F16(acc[mt][2*np+1], a0, a1, a2, a3, bfr[np][2], bfr[np][3]);
                }
            }
        }
        __syncthreads();
    }

    const int gr = lane >> 2;
    const int c2 = (lane & 3) * 2;
    float* p = g_part + ((size_t)blockIdx.x*BATCH + m0)*128 + n0;
#pragma unroll
    for (int mt = 0; mt < 2; ++mt)
#pragma unroll
        for (int nf = 0; nf < 8; ++nf) {
            int n = nf*8 + c2;
            float* pr = p + (size_t)(mt*16 + gr)*128 + n;
            *(float2*)(pr)        = make_float2(acc[mt][nf][0], acc[mt][nf][1]);
            *(float2*)(pr + 8*128) = make_float2(acc[mt][nf][2], acc[mt][nf][3]);
        }
}

// ===========================================================================
// dense1red: stage-1 reduction of 266 splits in 7 chunks of 38.
// grid (7, 128), 128 threads.
// ===========================================================================
__global__ void __launch_bounds__(128) dense1red_kernel()
{
    const int c = blockIdx.x;          // chunk 0..6
    const int b = blockIdx.y;
    const int t = threadIdx.x;
    if (t >= 120) return;

    const size_t stride = (size_t)BATCH * 128;
    const float* gp = g_part + ((size_t)(c*38)*BATCH + b)*128 + t;

    float s0 = 0.f, s1 = 0.f, s2 = 0.f, s3 = 0.f;
#pragma unroll 2
    for (int i = 0; i < 36; i += 4) {
        s0 += gp[(size_t)(i+0)*stride];
        s1 += gp[(size_t)(i+1)*stride];
        s2 += gp[(size_t)(i+2)*stride];
        s3 += gp[(size_t)(i+3)*stride];
    }
    s0 += gp[(size_t)36*stride];
    s1 += gp[(size_t)37*stride];
    g_red[((size_t)c*BATCH + b)*120 + t] = (s0 + s1) + (s2 + s3);
}

// ===========================================================================
// dense23: reduce 7 stage-1 partials + bias + relu -> h1;
//          h2 = relu(h1 @ d2_w + b2);  theta = h2 @ d3_w + b3.
// ===========================================================================
__global__ void __launch_bounds__(128) dense23_kernel(
    const float* __restrict__ d1b,
    const float* __restrict__ d2w, const float* __restrict__ d2b,
    const float* __restrict__ d3w, const float* __restrict__ d3b)
{
    __shared__ float h1[120];
    __shared__ float h2[84];
    const int b = blockIdx.x, t = threadIdx.x;

    if (t < 120) {
        const float* gp = g_red + (size_t)b*120 + t;
        float s = d1b[t];
#pragma unroll
        for (int i = 0; i < 7; ++i)
            s += gp[(size_t)i*BATCH*120];
        h1[t] = fmaxf(s, 0.f);
    }
    __syncthreads();
    if (t < 84) {
        float s = d2b[t];
#pragma unroll 4
        for (int k = 0; k < 120; ++k)
            s = fmaf(h1[k], d2w[k*84 + t], s);
        h2[t] = fmaxf(s, 0.f);
    }
    __syncthreads();
    if (t < 6) {
        float s = d3b[t];
#pragma unroll 4
        for (int k = 0; k < 84; ++k)
            s = fmaf(h2[k], d3w[k*6 + t], s);
        g_theta[b*6 + t] = s;
    }
}

// ===========================================================================
// sampler: affine grid + bilinear sample + 1x1 conv + sigmoid.
// ===========================================================================
__global__ void __launch_bounds__(256) sampler_kernel(
    const float* __restrict__ x, const float* __restrict__ ow,
    const float* __restrict__ ob, float* __restrict__ out)
{
    __shared__ float th[6];
    const int b = blockIdx.y;
    const int h = blockIdx.x;
    const int w = threadIdx.x;
    if (w < 6) th[w] = g_theta[b*6 + w];
    __syncthreads();

    const float gx = (float)w * (2.f/256.f) - 1.f;
    const float gy = (float)h * (2.f/256.f) - 1.f;
    const float px = (th[0]*gx + th[1]*gy + th[2] + 1.f) * 128.f;
    const float py = (th[3]*gx + th[4]*gy + th[5] + 1.f) * 128.f;

    const int fx = (int)floorf(px);
    const int fy = (int)floorf(py);
    const int x1 = min(max(fx,     0), HW-1);
    const int x2 = min(max(fx + 1, 0), HW-1);
    const int y1 = min(max(fy,     0), HW-1);
    const int y2 = min(max(fy + 1, 0), HW-1);

    const float* img = x + (size_t)b * (HW*HW);
    const float p11 = img[y1*HW + x1];
    const float p12 = img[y2*HW + x1];
    const float p21 = img[y1*HW + x2];
    const float p22 = img[y2*HW + x2];

    const float wx1 = (float)x2 - px;
    const float wx2 = px - (float)x1;
    const float wy1 = (float)y2 - py;
    const float wy2 = py - (float)y1;

    const float r = wx1*(wy1*p11 + wy2*p12) + wx2*(wy1*p21 + wy2*p22);
    const float t = r * __ldg(ow) + __ldg(ob);
    out[((size_t)b*HW + h)*HW + w] = 1.f / (1.f + expf(-t));
}

// ===========================================================================
// launch
// ===========================================================================
extern "C" void kernel_launch(void* const* d_in, const int* in_sizes, int n_in,
                              void* d_out, int out_size)
{
    const float* x      = (const float*)d_in[0];
    const float* c1w    = (const float*)d_in[1];
    const float* c1b    = (const float*)d_in[2];
    const float* c2w    = (const float*)d_in[3];
    const float* c2b    = (const float*)d_in[4];
    const float* d1w    = (const float*)d_in[5];
    const float* d1b    = (const float*)d_in[6];
    const float* d2w    = (const float*)d_in[7];
    const float* d2b    = (const float*)d_in[8];
    const float* d3w    = (const float*)d_in[9];
    const float* d3b    = (const float*)d_in[10];
    const float* outw   = (const float*)d_in[11];
    const float* outb   = (const float*)d_in[12];
    float* out = (float*)d_out;

    (void)in_sizes; (void)n_in; (void)out_size;

    cudaFuncSetAttribute(conv2_kernel,
                         cudaFuncAttributeMaxDynamicSharedMemorySize, C2_SMEM_B);
    cudaFuncSetAttribute(dense1_kernel,
                         cudaFuncAttributeMaxDynamicSharedMemorySize, D1_SMEM_B);

    wprep_kernel<<<25, 256>>>(c2w);
    wprep1_kernel<<<1, 512>>>(c1w);
    conv1_kernel<<<dim3(8, 16, BATCH), 256>>>(x, c1b);
    conv2_kernel<<<dim3(4, 8, BATCH), 256, C2_SMEM_B>>>(c2b);
    dense1_kernel<<<D1_SPLITS, 256, D1_SMEM_B>>>(d1w);
    dense1red_kernel<<<dim3(7, BATCH), 128>>>();
    dense23_kernel<<<BATCH, 128>>>(d1b, d2w, d2b, d3w, d3b);
    sampler_kernel<<<dim3(HW, BATCH), 256>>>(x, outw, outb, out);
}